// round 12
// baseline (speedup 1.0000x reference)
#include <cuda_runtime.h>
#include <cuda_bf16.h>
#include <cstdint>

#define BB 2
#define SS 4096
#define DD 512
#define HH 8
#define DK 64
#define BH (BB*HH)          // 16
#define MROWS (BB*SS)       // 8192

// log2(e) * 0.125 (softmax scale folded into base-2 domain)
#define SCL 0.18033688011112042f

// Scratch (device globals: allocation-free)
__device__ float g_q[(size_t)BH * SS * DK];
__device__ float g_k[(size_t)BH * SS * DK];
__device__ float g_v[(size_t)BH * SS * DK];
__device__ float g_ctx[(size_t)MROWS * DD];
__device__ float g_m[(size_t)BH * SS];
__device__ float g_linv[(size_t)BH * SS];
__device__ float g_opart[(size_t)BH * 32 * 4 * 128 * DK];
__device__ float g_mpart[(size_t)BH * 32 * 4 * 128];
__device__ float g_lpart[(size_t)BH * 32 * 4 * 128];
__device__ float g_rin[(size_t)3 * MROWS * DD];     // tf32-rounded Q,K,V inputs
__device__ float g_rw[(size_t)4 * DD * DD];         // tf32-rounded weights
__device__ float g_attn[(size_t)BH * SS * SS];      // used only if attn not in d_out

// ---------------------------------------------------------------------------
__device__ __forceinline__ uint32_t f2tf(float x) {
    uint32_t u;
    asm("cvt.rna.tf32.f32 %0, %1;" : "=r"(u) : "f"(x));
    return u;
}
__device__ __forceinline__ float tfr(float x) {
    return __uint_as_float(f2tf(x));
}
__device__ __forceinline__ float ex2(float x) {
    float y;
    asm("ex2.approx.ftz.f32 %0, %1;" : "=f"(y) : "f"(x));
    return y;
}
__device__ __forceinline__ void mma8(float* d,
    uint32_t a0, uint32_t a1, uint32_t a2, uint32_t a3,
    uint32_t b0, uint32_t b1)
{
    asm volatile(
        "mma.sync.aligned.m16n8k8.row.col.f32.tf32.tf32.f32 "
        "{%0,%1,%2,%3},{%4,%5,%6,%7},{%8,%9},{%0,%1,%2,%3};"
        : "+f"(d[0]), "+f"(d[1]), "+f"(d[2]), "+f"(d[3])
        : "r"(a0), "r"(a1), "r"(a2), "r"(a3), "r"(b0), "r"(b1));
}
__device__ __forceinline__ void ldsm4(uint32_t& r0, uint32_t& r1,
                                      uint32_t& r2, uint32_t& r3, uint32_t addr)
{
    asm volatile("ldmatrix.sync.aligned.m8n8.x4.shared.b16 {%0,%1,%2,%3}, [%4];"
        : "=r"(r0), "=r"(r1), "=r"(r2), "=r"(r3) : "r"(addr));
}
__device__ __forceinline__ void cpa16(uint32_t dst, const void* src) {
    asm volatile("cp.async.cg.shared.global [%0], [%1], 16;" :: "r"(dst), "l"(src));
}
#define CP_COMMIT() asm volatile("cp.async.commit_group;")
#define CP_WAIT0()  asm volatile("cp.async.wait_group 0;")

// ---------------------------------------------------------------------------
// Prepass: tf32-round Q,K,V inputs and the 4 weight matrices into scratch.
// ---------------------------------------------------------------------------
#define NINW ((size_t)3 * MROWS * DD)    // 12,582,912 floats
#define NWW  ((size_t)4 * DD * DD)       // 1,048,576 floats

__global__ __launch_bounds__(256) void round_pre(
    const float* __restrict__ Q, const float* __restrict__ K, const float* __restrict__ V,
    const float* __restrict__ wq, const float* __restrict__ wk,
    const float* __restrict__ wv, const float* __restrict__ wo,
    float* __restrict__ rin, float* __restrict__ rw)
{
    size_t idx = ((size_t)blockIdx.x * 256 + threadIdx.x) * 4;
    const size_t NPER = (size_t)MROWS * DD;   // 4,194,304
    if (idx < NINW) {
        const float* src = (idx < NPER) ? Q : (idx < 2 * NPER ? K : V);
        size_t off = idx & (NPER - 1);
        float4 v = *reinterpret_cast<const float4*>(&src[off]);
        float4 o = { tfr(v.x), tfr(v.y), tfr(v.z), tfr(v.w) };
        *reinterpret_cast<float4*>(&rin[idx]) = o;
    } else {
        size_t j = idx - NINW;
        const size_t WPER = (size_t)DD * DD;  // 262,144
        const float* src = (j < WPER) ? wq : (j < 2 * WPER ? wk : (j < 3 * WPER ? wv : wo));
        size_t off = j & (WPER - 1);
        float4 v = *reinterpret_cast<const float4*>(&src[off]);
        float4 o = { tfr(v.x), tfr(v.y), tfr(v.z), tfr(v.w) };
        *reinterpret_cast<float4*>(&rw[j]) = o;
    }
}

// ---------------------------------------------------------------------------
// Double-buffered TF32 GEMM: C[M x 512] = A[M x 512] @ W[512 x 512] + bias.
// smem (dynamic): A0[128*36] A1 | B0[32*136] B1  = 17920 words
// ---------------------------------------------------------------------------
#define GQ_A0 0
#define GQ_A1 4608
#define GQ_B0 9216
#define GQ_B1 13568
#define GEMM_SMEM_BYTES (17920 * 4)   // 71680

__device__ __forceinline__ void gemm_body_db(
    const float* __restrict__ A, const float* __restrict__ W,
    const float* __restrict__ bias, float* __restrict__ C,
    int round_split, uint32_t* sm)
{
    uint32_t sb = (uint32_t)__cvta_generic_to_shared(sm);
    int tid = threadIdx.x;
    int lane = tid & 31, warp = tid >> 5;
    int wm = (warp >> 2) * 64, wn = (warp & 3) * 32;
    int r = lane >> 2, c = lane & 3;
    int ag = lane >> 3, ar = lane & 7;
    int m0 = blockIdx.y * 128, n0 = blockIdx.x * 128;
    uint32_t a_lane = ((uint32_t)((ar + ((ag & 1) << 3)) * 36 + ((ag >> 1) << 2))) << 2;

    float acc[4][4][4] = {};

    #pragma unroll
    for (int it = 0; it < 4; it++) {
        int l = tid + it * 256;
        int arow = l >> 3, ac4 = (l & 7) * 4;
        cpa16(sb + (uint32_t)((GQ_A0 + arow * 36 + ac4) * 4),
              &A[(size_t)(m0 + arow) * DD + ac4]);
        int kr = l >> 5, nv = (l & 31) * 4;
        cpa16(sb + (uint32_t)((GQ_B0 + kr * 136 + nv) * 4),
              &W[(size_t)kr * DD + n0 + nv]);
    }
    CP_COMMIT();

    for (int kc = 0; kc < 16; kc++) {
        CP_WAIT0();
        __syncthreads();
        if (kc < 15) {
            int k0n = (kc + 1) * 32;
            int ao = ((kc + 1) & 1) ? GQ_A1 : GQ_A0;
            int bo = ((kc + 1) & 1) ? GQ_B1 : GQ_B0;
            #pragma unroll
            for (int it = 0; it < 4; it++) {
                int l = tid + it * 256;
                int arow = l >> 3, ac4 = (l & 7) * 4;
                cpa16(sb + (uint32_t)((ao + arow * 36 + ac4) * 4),
                      &A[(size_t)(m0 + arow) * DD + k0n + ac4]);
                int kr = l >> 5, nv = (l & 31) * 4;
                cpa16(sb + (uint32_t)((bo + kr * 136 + nv) * 4),
                      &W[(size_t)(k0n + kr) * DD + n0 + nv]);
            }
            CP_COMMIT();
        }
        uint32_t ab_s = sb + (uint32_t)((((kc & 1) ? GQ_A1 : GQ_A0)) * 4);
        const uint32_t* Bb = sm + ((kc & 1) ? GQ_B1 : GQ_B0);
        #pragma unroll
        for (int kk = 0; kk < 32; kk += 8) {
            uint32_t a[4][4], b[4][2];
            #pragma unroll
            for (int im = 0; im < 4; im++)
                ldsm4(a[im][0], a[im][1], a[im][2], a[im][3],
                      ab_s + (uint32_t)(((wm + im * 16) * 36 + kk) * 4) + a_lane);
            #pragma unroll
            for (int in = 0; in < 4; in++) {
                int nb = wn + in * 8;
                b[in][0] = Bb[(kk + c) * 136 + nb + r];
                b[in][1] = Bb[(kk + c + 4) * 136 + nb + r];
            }
            #pragma unroll
            for (int im = 0; im < 4; im++)
                #pragma unroll
                for (int in = 0; in < 4; in++)
                    mma8(acc[im][in], a[im][0], a[im][1], a[im][2], a[im][3],
                         b[in][0], b[in][1]);
        }
    }

    #pragma unroll
    for (int im = 0; im < 4; im++) {
        #pragma unroll
        for (int in = 0; in < 4; in++) {
            int row0 = m0 + wm + im * 16 + r;
            int col0 = n0 + wn + in * 8 + 2 * c;
            float bz0 = bias[col0], bz1 = bias[col0 + 1];
            #pragma unroll
            for (int half = 0; half < 2; half++) {
                int row = row0 + half * 8;
                float2 v;
                v.x = acc[im][in][half * 2 + 0] + bz0;
                v.y = acc[im][in][half * 2 + 1] + bz1;
                if (round_split) {
                    v.x = tfr(v.x); v.y = tfr(v.y);
                    int bb = row >> 12, s = row & (SS - 1);
                    int h = col0 >> 6, dk = col0 & 63;
                    *reinterpret_cast<float2*>(
                        &C[(((size_t)(bb * HH + h)) * SS + s) * DK + dk]) = v;
                } else {
                    *reinterpret_cast<float2*>(&C[(size_t)row * DD + col0]) = v;
                }
            }
        }
    }
}

__global__ __launch_bounds__(256, 2) void gemm_qkv(
    const float* __restrict__ rin, const float* __restrict__ rw,
    const float* __restrict__ bq, const float* __restrict__ bk, const float* __restrict__ bv,
    float* __restrict__ cq, float* __restrict__ ck, float* __restrict__ cv)
{
    extern __shared__ uint32_t dsm[];
    int z = blockIdx.z;
    const float* A = rin + (size_t)z * MROWS * DD;
    const float* W = rw + (size_t)z * DD * DD;
    const float* bias = (z == 0) ? bq : (z == 1 ? bk : bv);
    float* C = (z == 0) ? cq : (z == 1 ? ck : cv);
    gemm_body_db(A, W, bias, C, 1, dsm);
}

__global__ __launch_bounds__(256, 2) void gemm_out(
    const float* __restrict__ A, const float* __restrict__ rw,
    const float* __restrict__ bias, float* __restrict__ C)
{
    extern __shared__ uint32_t dsm[];
    gemm_body_db(A, rw + (size_t)3 * DD * DD, bias, C, 0, dsm);
}

// ---------------------------------------------------------------------------
// Split-K single-pass flash attention.
// ---------------------------------------------------------------------------
#define FL_SMEM_WORDS (8704 + 2*4352 + 2*4608)
#define FL_SMEM_BYTES (FL_SMEM_WORDS * 4)
#define K0_OFF 8704
#define K1_OFF 13056
#define V0_OFF 17408
#define V1_OFF 22016

__global__ __launch_bounds__(256, 2) void flash_attn(
    const float* __restrict__ q, const float* __restrict__ k,
    const float* __restrict__ v, float* __restrict__ ctx,
    float* __restrict__ gm, float* __restrict__ glinv,
    float* __restrict__ opart, float* __restrict__ mpart, float* __restrict__ lpart)
{
    extern __shared__ uint32_t smem[];
    uint32_t sb = (uint32_t)__cvta_generic_to_shared(smem);
    int tid = threadIdx.x;
    int lane = tid & 31, wq = tid >> 5;
    int r = lane >> 2, c = lane & 3;
    int ag = lane >> 3, ar = lane & 7;

    int f = 79 - (int)blockIdx.x;
    int by, ch, nch;
    if (f < 8)       { by = f;              ch = 0;     nch = 1; }
    else if (f < 24) { int t = f - 8;  by = 8  + (t >> 1); ch = t & 1; nch = 2; }
    else if (f < 48) { int t = f - 24; by = 16 + t / 3;    ch = t % 3; nch = 3; }
    else             { int t = f - 48; by = 24 + (t >> 2); ch = t & 3; nch = 4; }
    int bh = blockIdx.y;
    int ktot = 2 * by + 2;
    int kt0 = ch * ktot / nch;
    int kt1 = (ch + 1) * ktot / nch;
    int nt = kt1 - kt0;

    const float* qb = q + (size_t)bh * SS * DK;
    const float* kb = k + (size_t)bh * SS * DK;
    const float* vb = v + (size_t)bh * SS * DK;

    int i0 = by * 128 + wq * 16 + r, i1 = i0 + 8;

    uint32_t qaddr = sb + (((wq * 16 + ar + ((ag & 1) << 3)) * 68 + ((ag >> 1) << 2)) << 2);
    uint32_t koff_l = ((((ag >> 1) << 3) + ar) * 68 + ((ag & 1) << 2)) << 2;

    #pragma unroll
    for (int l = tid; l < 2048; l += 256) {
        int rr = l >> 4, c4 = (l & 15) * 4;
        cpa16(sb + (rr * 68 + c4) * 4, &qb[(size_t)(by * 128 + rr) * DK + c4]);
    }
    {
        int kt = kt0;
        #pragma unroll
        for (int l = tid; l < 1024; l += 256) {
            int rr = l >> 4, c4 = (l & 15) * 4;
            cpa16(sb + (K0_OFF + rr * 68 + c4) * 4, &kb[(size_t)(kt * 64 + rr) * DK + c4]);
            cpa16(sb + (V0_OFF + rr * 72 + c4) * 4, &vb[(size_t)(kt * 64 + rr) * DK + c4]);
        }
    }
    CP_COMMIT();

    float m0 = -1e30f, m1 = -1e30f, l0 = 0.f, l1 = 0.f;
    float o[8][4];
    #pragma unroll
    for (int n = 0; n < 8; n++)
        #pragma unroll
        for (int qq = 0; qq < 4; qq++) o[n][qq] = 0.f;

    int sq1 = (lane & 28) | (c >> 1);
    int sq2 = sq1 + 2;
    int comp = c & 1;

    for (int t = 0; t < nt; t++) {
        CP_WAIT0();
        __syncthreads();
        if (t + 1 < nt) {
            int kt = kt0 + t + 1;
            int koffs = ((t + 1) & 1) ? K1_OFF : K0_OFF;
            int voffs = ((t + 1) & 1) ? V1_OFF : V0_OFF;
            #pragma unroll
            for (int l = tid; l < 1024; l += 256) {
                int rr = l >> 4, c4 = (l & 15) * 4;
                cpa16(sb + (koffs + rr * 68 + c4) * 4, &kb[(size_t)(kt * 64 + rr) * DK + c4]);
                cpa16(sb + (voffs + rr * 72 + c4) * 4, &vb[(size_t)(kt * 64 + rr) * DK + c4]);
            }
            CP_COMMIT();
        }

        int kt = kt0 + t;
        uint32_t kb_b = sb + ((t & 1) ? K1_OFF : K0_OFF) * 4;
        const uint32_t* Vb = smem + ((t & 1) ? V1_OFF : V0_OFF);

        float s[8][4];
        #pragma unroll
        for (int n = 0; n < 8; n++)
            #pragma unroll
            for (int qq = 0; qq < 4; qq++) s[n][qq] = 0.f;
        #pragma unroll
        for (int kk8 = 0; kk8 < 8; kk8++) {
            uint32_t a0, a1, a2, a3;
            ldsm4(a0, a1, a2, a3, qaddr + kk8 * 32);
            uint32_t b[8][2];
            #pragma unroll
            for (int p = 0; p < 4; p++)
                ldsm4(b[2*p][0], b[2*p][1], b[2*p+1][0], b[2*p+1][1],
                      kb_b + p * 4352 + koff_l + kk8 * 32);
            #pragma unroll
            for (int n = 0; n < 8; n++)
                mma8(s[n], a0, a1, a2, a3, b[n][0], b[n][1]);
        }

        bool diag = (kt >= 2 * by);
        float mx0 = -1e30f, mx1 = -1e30f;
        #pragma unroll
        for (int n = 0; n < 8; n++) {
            int j0 = kt * 64 + n * 8 + 2 * c;
            float t0 = s[n][0] * SCL, t1 = s[n][1] * SCL;
            float t2 = s[n][2] * SCL, t3 = s[n][3] * SCL;
            if (diag) {
                if (j0     > i0) t0 = -1e30f;
                if (j0 + 1 > i0) t1 = -1e30f;
                if (j0     > i1) t2 = -1e30f;
                if (j0 + 1 > i1) t3 = -1e30f;
            }
            s[n][0] = t0; s[n][1] = t1; s[n][2] = t2; s[n][3] = t3;
            mx0 = fmaxf(mx0, fmaxf(t0, t1));
            mx1 = fmaxf(mx1, fmaxf(t2, t3));
        }
        mx0 = fmaxf(mx0, __shfl_xor_sync(0xffffffffu, mx0, 1));
        mx0 = fmaxf(mx0, __shfl_xor_sync(0xffffffffu, mx0, 2));
        mx1 = fmaxf(mx1, __shfl_xor_sync(0xffffffffu, mx1, 1));
        mx1 = fmaxf(mx1, __shfl_xor_sync(0xffffffffu, mx1, 2));
        float mn0 = fmaxf(m0, mx0), mn1 = fmaxf(m1, mx1);
        float f0 = ex2(m0 - mn0), f1 = ex2(m1 - mn1);

        uint32_t pt[8][4];
        float sum0 = 0.f, sum1 = 0.f;
        #pragma unroll
        for (int n = 0; n < 8; n++) {
            float p0 = ex2(s[n][0] - mn0);
            float p1 = ex2(s[n][1] - mn0);
            float p2 = ex2(s[n][2] - mn1);
            float p3 = ex2(s[n][3] - mn1);
            sum0 += p0 + p1; sum1 += p2 + p3;
            pt[n][0] = f2tf(p0); pt[n][1] = f2tf(p1);
            pt[n][2] = f2tf(p2); pt[n][3] = f2tf(p3);
        }
        sum0 += __shfl_xor_sync(0xffffffffu, sum0, 1);
        sum0 += __shfl_xor_sync(0xffffffffu, sum0, 2);
        sum1 += __shfl_xor_sync(0xffffffffu, sum1, 1);
        sum1 += __shfl_xor_sync(0xffffffffu, sum1, 2);
        l0 = l0 * f0 + sum0; m0 = mn0;
        l1 = l1 * f1 + sum1; m1 = mn1;

        #pragma unroll
        for (int n = 0; n < 8; n++) {
            o[n][0] *= f0; o[n][1] *= f0;
            o[n][2] *= f1; o[n][3] *= f1;
        }

        #pragma unroll
        for (int g = 0; g < 8; g++) {
            uint32_t v0, v1, a0, a1, a2, a3;
            v0 = __shfl_sync(0xffffffffu, pt[g][0], sq1);
            v1 = __shfl_sync(0xffffffffu, pt[g][1], sq1);
            a0 = comp ? v1 : v0;
            v0 = __shfl_sync(0xffffffffu, pt[g][2], sq1);
            v1 = __shfl_sync(0xffffffffu, pt[g][3], sq1);
            a1 = comp ? v1 : v0;
            v0 = __shfl_sync(0xffffffffu, pt[g][0], sq2);
            v1 = __shfl_sync(0xffffffffu, pt[g][1], sq2);
            a2 = comp ? v1 : v0;
            v0 = __shfl_sync(0xffffffffu, pt[g][2], sq2);
            v1 = __shfl_sync(0xffffffffu, pt[g][3], sq2);
            a3 = comp ? v1 : v0;
            int kk = g * 8;
            #pragma unroll
            for (int n = 0; n < 8; n++) {
                uint32_t b0 = Vb[(kk + c) * 72 + n * 8 + r];
                uint32_t b1 = Vb[(kk + c + 4) * 72 + n * 8 + r];
                mma8(o[n], a0, a1, a2, a3, b0, b1);
            }
        }
    }

    if (nch == 1) {
        float inv0 = 1.0f / l0, inv1 = 1.0f / l1;
        if (c == 0) {
            gm[(size_t)bh * SS + i0] = m0;  glinv[(size_t)bh * SS + i0] = inv0;
            gm[(size_t)bh * SS + i1] = m1;  glinv[(size_t)bh * SS + i1] = inv1;
        }
        int bb = bh >> 3, h = bh & 7;
        #pragma unroll
        for (int n = 0; n < 8; n++) {
            int dk = n * 8 + 2 * c;
            float2 w0 = { tfr(o[n][0] * inv0), tfr(o[n][1] * inv0) };
            float2 w1 = { tfr(o[n][2] * inv1), tfr(o[n][3] * inv1) };
            *reinterpret_cast<float2*>(&ctx[((size_t)(bb * SS + i0)) * DD + h * 64 + dk]) = w0;
            *reinterpret_cast<float2*>(&ctx[((size_t)(bb * SS + i1)) * DD + h * 64 + dk]) = w1;
        }
    } else {
        size_t pidx = ((size_t)(bh * 32 + by)) * 4 + ch;
        int lr0 = wq * 16 + r, lr1 = lr0 + 8;
        if (c == 0) {
            mpart[pidx * 128 + lr0] = m0;  lpart[pidx * 128 + lr0] = l0;
            mpart[pidx * 128 + lr1] = m1;  lpart[pidx * 128 + lr1] = l1;
        }
        float* ob = opart + (pidx * 128) * DK;
        #pragma unroll
        for (int n = 0; n < 8; n++) {
            int dk = n * 8 + 2 * c;
            float2 w0 = { o[n][0], o[n][1] };
            float2 w1 = { o[n][2], o[n][3] };
            *reinterpret_cast<float2*>(&ob[(size_t)lr0 * DK + dk]) = w0;
            *reinterpret_cast<float2*>(&ob[(size_t)lr1 * DK + dk]) = w1;
        }
    }
}

// ---------------------------------------------------------------------------
// Combine partial (m, l, O) chunks for by >= 8.
// ---------------------------------------------------------------------------
__global__ __launch_bounds__(256) void flash_combine(
    const float* __restrict__ opart, const float* __restrict__ mpart,
    const float* __restrict__ lpart, float* __restrict__ ctx,
    float* __restrict__ gm, float* __restrict__ glinv)
{
    int by = 8 + blockIdx.x;
    int bh = blockIdx.y;
    int nch = by / 8 + 1;
    int tid = threadIdx.x;
    int row = tid >> 1, half = tid & 1;
    size_t p0 = ((size_t)(bh * 32 + by)) * 4;

    float mf = -1e30f;
    #pragma unroll 4
    for (int chv = 0; chv < 4; chv++)
        if (chv < nch) mf = fmaxf(mf, mpart[(p0 + chv) * 128 + row]);
    float L = 0.f;
    float wch[4];
    #pragma unroll 4
    for (int chv = 0; chv < 4; chv++) {
        if (chv < nch) {
            float w = ex2(mpart[(p0 + chv) * 128 + row] - mf);
            wch[chv] = w;
            L += lpart[(p0 + chv) * 128 + row] * w;
        } else wch[chv] = 0.f;
    }
    float invL = 1.0f / L;

    float acc[32];
    #pragma unroll
    for (int j = 0; j < 32; j++) acc[j] = 0.f;
    #pragma unroll 4
    for (int chv = 0; chv < 4; chv++) {
        if (chv >= nch) break;
        const float* ob = opart + ((p0 + chv) * 128 + row) * DK + half * 32;
        float w = wch[chv];
        #pragma unroll
        for (int j4 = 0; j4 < 8; j4++) {
            float4 vv = *reinterpret_cast<const float4*>(&ob[j4 * 4]);
            acc[j4*4+0] += vv.x * w; acc[j4*4+1] += vv.y * w;
            acc[j4*4+2] += vv.z * w; acc[j4*4+3] += vv.w * w;
        }
    }

    int i = by * 128 + row;
    int bb = bh >> 3, h = bh & 7;
    float* cp = ctx + ((size_t)(bb * SS + i)) * DD + h * 64 + half * 32;
    #pragma unroll
    for (int j4 = 0; j4 < 8; j4++) {
        float4 vv = { tfr(acc[j4*4+0] * invL), tfr(acc[j4*4+1] * invL),
                      tfr(acc[j4*4+2] * invL), tfr(acc[j4*4+3] * invL) };
        *reinterpret_cast<float4*>(&cp[j4 * 4]) = vv;
    }
    if (half == 0) {
        gm[(size_t)bh * SS + i] = mf;
        glinv[(size_t)bh * SS + i] = invL;
    }
}

// ---------------------------------------------------------------------------
// Bounded-share persistent zero-fill of upper-triangle attn tiles.
// Small grid (74 blocks) so it coexists with flash instead of displacing it.
// ---------------------------------------------------------------------------
__global__ __launch_bounds__(256) void attn_zero_small(float* __restrict__ attn)
{
    int tid = threadIdx.x;
    float4 z = { 0.f, 0.f, 0.f, 0.f };
    for (int t = blockIdx.x; t < 16 * 1024; t += gridDim.x) {
        int bh = t >> 10;
        int r6 = t & 1023;
        int by = r6 >> 5, bx = r6 & 31;
        if (bx <= by) continue;   // lower tiles belong to attn_write
        float* ab = attn + (size_t)bh * SS * SS;
        #pragma unroll 4
        for (int l = tid; l < 4096; l += 256) {
            int rr = l >> 5, c4 = (l & 31) * 4;
            __stcs(reinterpret_cast<float4*>(
                &ab[(size_t)(by * 128 + rr) * SS + bx * 128 + c4]), z);
        }
    }
}

// ---------------------------------------------------------------------------
// attn writer: lower-triangle tiles only (upper handled by attn_zero_small).
// Recompute S, p = ex2(t-m)*linv, stage in smem (stride 136), coalesced stores.
// ---------------------------------------------------------------------------
#define AW_SMEM_WORDS (8704 * 2)
#define AW_SMEM_BYTES (AW_SMEM_WORDS * 4)

__global__ __launch_bounds__(256, 2) void attn_write(
    const float* __restrict__ q, const float* __restrict__ k,
    const float* __restrict__ gm, const float* __restrict__ glinv,
    float* __restrict__ attn)
{
    int bx = blockIdx.x, by = blockIdx.y, bh = blockIdx.z;
    if (bx > by) return;   // upper tiles: attn_zero_small
    float* ab = attn + (size_t)bh * SS * SS;
    int tid = threadIdx.x;

    extern __shared__ uint32_t sm2[];
    uint32_t* Qs = sm2;
    uint32_t* Ks = sm2 + 8704;
    const float* qb = q + (size_t)bh * SS * DK;
    const float* kb = k + (size_t)bh * SS * DK;

    #pragma unroll 4
    for (int l = tid; l < 2048; l += 256) {
        int rr = l >> 4, c4 = (l & 15) * 4;
        *reinterpret_cast<uint4*>(&Qs[rr * 68 + c4]) =
            *reinterpret_cast<const uint4*>(&qb[(size_t)(by * 128 + rr) * DK + c4]);
        *reinterpret_cast<uint4*>(&Ks[rr * 68 + c4]) =
            *reinterpret_cast<const uint4*>(&kb[(size_t)(bx * 128 + rr) * DK + c4]);
    }
    __syncthreads();

    int lane = tid & 31, warp = tid >> 5;
    int wm = (warp >> 2) * 64, wn = (warp & 3) * 32;
    int r = lane >> 2, c = lane & 3;

    float acc[4][4][4];
    #pragma unroll
    for (int im = 0; im < 4; im++)
        #pragma unroll
        for (int in = 0; in < 4; in++)
            #pragma unroll
            for (int qq = 0; qq < 4; qq++) acc[im][in][qq] = 0.f;

    #pragma unroll
    for (int kk = 0; kk < 64; kk += 8) {
        uint32_t a[4][4], b[4][2];
        #pragma unroll
        for (int im = 0; im < 4; im++) {
            int mb = wm + im * 16;
            a[im][0] = Qs[(mb + r) * 68 + kk + c];
            a[im][1] = Qs[(mb + r + 8) * 68 + kk + c];
            a[im][2] = Qs[(mb + r) * 68 + kk + c + 4];
            a[im][3] = Qs[(mb + r + 8) * 68 + kk + c + 4];
        }
        #pragma unroll
        for (int in = 0; in < 4; in++) {
            int nb = wn + in * 8;
            b[in][0] = Ks[(nb + r) * 68 + kk + c];
            b[in][1] = Ks[(nb + r) * 68 + kk + c + 4];
        }
        #pragma unroll
        for (int im = 0; im < 4; im++)
            #pragma unroll
            for (int in = 0; in < 4; in++)
                mma8(acc[im][in], a[im][0], a[im][1], a[im][2], a[im][3],
                     b[in][0], b[in][1]);
    }

    __syncthreads();  // everyone done reading Qs/Ks
    float* Ps = reinterpret_cast<float*>(sm2);
    bool dg = (bx == by);
    #pragma unroll
    for (int im = 0; im < 4; im++) {
        int i0 = by * 128 + wm + im * 16 + r;
        int i1 = i0 + 8;
        int lr0 = wm + im * 16 + r, lr1 = lr0 + 8;
        float m_0 = gm[(size_t)bh * SS + i0], li0 = glinv[(size_t)bh * SS + i0];
        float m_1 = gm[(size_t)bh * SS + i1], li1 = glinv[(size_t)bh * SS + i1];
        #pragma unroll
        for (int in = 0; in < 4; in++) {
            int j = wn + in * 8 + 2 * c;
            int j0 = bx * 128 + j;
            float p0 = ex2(acc[im][in][0] * SCL - m_0) * li0;
            float p1 = ex2(acc[im][in][1] * SCL - m_0) * li0;
            float p2 = ex2(acc[im][in][2] * SCL - m_1) * li1;
            float p3 = ex2(acc[im][in][3] * SCL - m_1) * li1;
            if (dg) {
                if (j0     > i0) p0 = 0.f;
                if (j0 + 1 > i0) p1 = 0.f;
                if (j0     > i1) p2 = 0.f;
                if (j0 + 1 > i1) p3 = 0.f;
            }
            float2 w01 = { p0, p1 };
            float2 w23 = { p2, p3 };
            *reinterpret_cast<float2*>(&Ps[lr0 * 136 + j]) = w01;
            *reinterpret_cast<float2*>(&Ps[lr1 * 136 + j]) = w23;
        }
    }
    __syncthreads();

    #pragma unroll 4
    for (int l = tid; l < 4096; l += 256) {
        int rr = l >> 5, c4 = (l & 31) * 4;
        float4 vv = *reinterpret_cast<const float4*>(&Ps[rr * 136 + c4]);
        __stcs(reinterpret_cast<float4*>(
            &ab[(size_t)(by * 128 + rr) * SS + bx * 128 + c4]), vv);
    }
}

// ---------------------------------------------------------------------------
extern "C" void kernel_launch(void* const* d_in, const int* in_sizes, int n_in,
                              void* d_out, int out_size)
{
    (void)in_sizes; (void)n_in;
    const float* Q  = (const float*)d_in[0];
    const float* K  = (const float*)d_in[1];
    const float* V  = (const float*)d_in[2];
    const float* wq = (const float*)d_in[3];
    const float* bq = (const float*)d_in[4];
    const float* wk = (const float*)d_in[5];
    const float* bk = (const float*)d_in[6];
    const float* wv = (const float*)d_in[7];
    const float* bv = (const float*)d_in[8];
    const float* wo = (const float*)d_in[9];
    const float* bo = (const float*)d_in[10];
    float* out = (float*)d_out;

    const size_t outN  = (size_t)MROWS * DD;
    const size_t attnN = (size_t)BH * SS * SS;

    int write_attn;
    float* attn;
    if ((size_t)out_size >= outN + attnN) {
        attn = out + outN;
        write_attn = 1;
    } else {
        void* p = nullptr;
        cudaGetSymbolAddress(&p, g_attn);
        attn = (float*)p;
        write_attn = 0;
    }

    float *qp, *kp, *vp, *ctxp, *mp, *lp, *op, *mpp, *lpp, *rin, *rw;
    { void* p; cudaGetSymbolAddress(&p, g_q);     qp   = (float*)p; }
    { void* p; cudaGetSymbolAddress(&p, g_k);     kp   = (float*)p; }
    { void* p; cudaGetSymbolAddress(&p, g_v);     vp   = (float*)p; }
    { void* p; cudaGetSymbolAddress(&p, g_ctx);   ctxp = (float*)p; }
    { void* p; cudaGetSymbolAddress(&p, g_m);     mp   = (float*)p; }
    { void* p; cudaGetSymbolAddress(&p, g_linv);  lp   = (float*)p; }
    { void* p; cudaGetSymbolAddress(&p, g_opart); op   = (float*)p; }
    { void* p; cudaGetSymbolAddress(&p, g_mpart); mpp  = (float*)p; }
    { void* p; cudaGetSymbolAddress(&p, g_lpart); lpp  = (float*)p; }
    { void* p; cudaGetSymbolAddress(&p, g_rin);   rin  = (float*)p; }
    { void* p; cudaGetSymbolAddress(&p, g_rw);    rw   = (float*)p; }

    cudaFuncSetAttribute(flash_attn, cudaFuncAttributeMaxDynamicSharedMemorySize,
                         FL_SMEM_BYTES);
    cudaFuncSetAttribute(attn_write, cudaFuncAttributeMaxDynamicSharedMemorySize,
                         AW_SMEM_BYTES);
    cudaFuncSetAttribute(gemm_qkv, cudaFuncAttributeMaxDynamicSharedMemorySize,
                         GEMM_SMEM_BYTES);
    cudaFuncSetAttribute(gemm_out, cudaFuncAttributeMaxDynamicSharedMemorySize,
                         GEMM_SMEM_BYTES);

    dim3 blk(256);
    size_t totalRound = (NINW + NWW) / 4;
    dim3 gQKV(DD / 128, MROWS / 128, 3);
    dim3 gFA(80, BH);
    dim3 gCB(24, BH);
    dim3 gOut(DD / 128, MROWS / 128);

    if (write_attn) {
        cudaStream_t s2;
        cudaStreamCreate(&s2);
        cudaEvent_t eA, eB, eC;
        cudaEventCreateWithFlags(&eA, cudaEventDisableTiming);
        cudaEventCreateWithFlags(&eB, cudaEventDisableTiming);
        cudaEventCreateWithFlags(&eC, cudaEventDisableTiming);

        // fork: bounded-share zero-fill overlaps the compute chain
        cudaEventRecord(eA, 0);
        cudaStreamWaitEvent(s2, eA, 0);
        attn_zero_small<<<74, blk, 0, s2>>>(attn);

        round_pre<<<(unsigned)(totalRound / 256), blk>>>(Q, K, V, wq, wk, wv, wo, rin, rw);
        gemm_qkv<<<gQKV, blk, GEMM_SMEM_BYTES>>>(rin, rw, bq, bk, bv, qp, kp, vp);
        flash_attn<<<gFA, blk, FL_SMEM_BYTES>>>(qp, kp, vp, ctxp, mp, lp, op, mpp, lpp);
        flash_combine<<<gCB, blk>>>(op, mpp, lpp, ctxp, mp, lp);

        // side stream: gemm_out after combine (and after zero-fill, via s2 order)
        cudaEventRecord(eB, 0);
        cudaStreamWaitEvent(s2, eB, 0);
        gemm_out<<<gOut, blk, GEMM_SMEM_BYTES, s2>>>(ctxp, rw, bo, out);
        cudaEventRecord(eC, s2);

        dim3 gAW(SS / 128, SS / 128, BH);
        attn_write<<<gAW, blk, AW_SMEM_BYTES>>>(qp, kp, mp, lp, attn);

        cudaStreamWaitEvent(0, eC, 0);
    } else {
        round_pre<<<(unsigned)(totalRound / 256), blk>>>(Q, K, V, wq, wk, wv, wo, rin, rw);
        gemm_qkv<<<gQKV, blk, GEMM_SMEM_BYTES>>>(rin, rw, bq, bk, bv, qp, kp, vp);
        flash_attn<<<gFA, blk, FL_SMEM_BYTES>>>(qp, kp, vp, ctxp, mp, lp, op, mpp, lpp);
        flash_combine<<<gCB, blk>>>(op, mpp, lpp, ctxp, mp, lp);
        gemm_out<<<gOut, blk, GEMM_SMEM_BYTES>>>(ctxp, rw, bo, out);
    }
}

// round 14
// speedup vs baseline: 1.0454x; 1.0454x over previous
#include <cuda_runtime.h>
#include <cuda_bf16.h>
#include <cstdint>

#define BB 2
#define SS 4096
#define DD 512
#define HH 8
#define DK 64
#define BH (BB*HH)          // 16
#define MROWS (BB*SS)       // 8192

// log2(e) * 0.125 (softmax scale folded into base-2 domain)
#define SCL 0.18033688011112042f

// Scratch (device globals: allocation-free)
__device__ float g_q[(size_t)BH * SS * DK];
__device__ float g_k[(size_t)BH * SS * DK];
__device__ float g_v[(size_t)BH * SS * DK];
__device__ float g_ctx[(size_t)MROWS * DD];
__device__ float g_m[(size_t)BH * SS];
__device__ float g_linv[(size_t)BH * SS];
__device__ float g_opart[(size_t)BH * 32 * 4 * 128 * DK];
__device__ float g_mpart[(size_t)BH * 32 * 4 * 128];
__device__ float g_lpart[(size_t)BH * 32 * 4 * 128];
__device__ float g_rin[(size_t)3 * MROWS * DD];     // tf32-rounded Q,K,V inputs
__device__ float g_rw[(size_t)4 * DD * DD];         // tf32-rounded weights
__device__ float g_attn[(size_t)BH * SS * SS];      // used only if attn not in d_out

// ---------------------------------------------------------------------------
__device__ __forceinline__ uint32_t f2tf(float x) {
    uint32_t u;
    asm("cvt.rna.tf32.f32 %0, %1;" : "=r"(u) : "f"(x));
    return u;
}
__device__ __forceinline__ float tfr(float x) {
    return __uint_as_float(f2tf(x));
}
__device__ __forceinline__ float ex2(float x) {
    float y;
    asm("ex2.approx.ftz.f32 %0, %1;" : "=f"(y) : "f"(x));
    return y;
}
__device__ __forceinline__ void mma8(float* d,
    uint32_t a0, uint32_t a1, uint32_t a2, uint32_t a3,
    uint32_t b0, uint32_t b1)
{
    asm volatile(
        "mma.sync.aligned.m16n8k8.row.col.f32.tf32.tf32.f32 "
        "{%0,%1,%2,%3},{%4,%5,%6,%7},{%8,%9},{%0,%1,%2,%3};"
        : "+f"(d[0]), "+f"(d[1]), "+f"(d[2]), "+f"(d[3])
        : "r"(a0), "r"(a1), "r"(a2), "r"(a3), "r"(b0), "r"(b1));
}
__device__ __forceinline__ void ldsm4(uint32_t& r0, uint32_t& r1,
                                      uint32_t& r2, uint32_t& r3, uint32_t addr)
{
    asm volatile("ldmatrix.sync.aligned.m8n8.x4.shared.b16 {%0,%1,%2,%3}, [%4];"
        : "=r"(r0), "=r"(r1), "=r"(r2), "=r"(r3) : "r"(addr));
}
__device__ __forceinline__ void cpa16(uint32_t dst, const void* src) {
    asm volatile("cp.async.cg.shared.global [%0], [%1], 16;" :: "r"(dst), "l"(src));
}
#define CP_COMMIT() asm volatile("cp.async.commit_group;")
#define CP_WAIT0()  asm volatile("cp.async.wait_group 0;")

// ---------------------------------------------------------------------------
// Prepass: tf32-round Q,K,V inputs and the 4 weight matrices into scratch.
// ---------------------------------------------------------------------------
#define NINW ((size_t)3 * MROWS * DD)    // 12,582,912 floats
#define NWW  ((size_t)4 * DD * DD)       // 1,048,576 floats

__global__ __launch_bounds__(256) void round_pre(
    const float* __restrict__ Q, const float* __restrict__ K, const float* __restrict__ V,
    const float* __restrict__ wq, const float* __restrict__ wk,
    const float* __restrict__ wv, const float* __restrict__ wo,
    float* __restrict__ rin, float* __restrict__ rw)
{
    size_t idx = ((size_t)blockIdx.x * 256 + threadIdx.x) * 4;
    const size_t NPER = (size_t)MROWS * DD;   // 4,194,304
    if (idx < NINW) {
        const float* src = (idx < NPER) ? Q : (idx < 2 * NPER ? K : V);
        size_t off = idx & (NPER - 1);
        float4 v = *reinterpret_cast<const float4*>(&src[off]);
        float4 o = { tfr(v.x), tfr(v.y), tfr(v.z), tfr(v.w) };
        *reinterpret_cast<float4*>(&rin[idx]) = o;
    } else {
        size_t j = idx - NINW;
        const size_t WPER = (size_t)DD * DD;  // 262,144
        const float* src = (j < WPER) ? wq : (j < 2 * WPER ? wk : (j < 3 * WPER ? wv : wo));
        size_t off = j & (WPER - 1);
        float4 v = *reinterpret_cast<const float4*>(&src[off]);
        float4 o = { tfr(v.x), tfr(v.y), tfr(v.z), tfr(v.w) };
        *reinterpret_cast<float4*>(&rw[j]) = o;
    }
}

// ---------------------------------------------------------------------------
// Double-buffered TF32 GEMM: C[M x 512] = A[M x 512] @ W[512 x 512] + bias.
// smem (dynamic): A0[128*36] A1 | B0[32*136] B1  = 17920 words
// ---------------------------------------------------------------------------
#define GQ_A0 0
#define GQ_A1 4608
#define GQ_B0 9216
#define GQ_B1 13568
#define GEMM_SMEM_BYTES (17920 * 4)   // 71680

__device__ __forceinline__ void gemm_body_db(
    const float* __restrict__ A, const float* __restrict__ W,
    const float* __restrict__ bias, float* __restrict__ C,
    int round_split, uint32_t* sm)
{
    uint32_t sb = (uint32_t)__cvta_generic_to_shared(sm);
    int tid = threadIdx.x;
    int lane = tid & 31, warp = tid >> 5;
    int wm = (warp >> 2) * 64, wn = (warp & 3) * 32;
    int r = lane >> 2, c = lane & 3;
    int ag = lane >> 3, ar = lane & 7;
    int m0 = blockIdx.y * 128, n0 = blockIdx.x * 128;
    uint32_t a_lane = ((uint32_t)((ar + ((ag & 1) << 3)) * 36 + ((ag >> 1) << 2))) << 2;

    float acc[4][4][4] = {};

    #pragma unroll
    for (int it = 0; it < 4; it++) {
        int l = tid + it * 256;
        int arow = l >> 3, ac4 = (l & 7) * 4;
        cpa16(sb + (uint32_t)((GQ_A0 + arow * 36 + ac4) * 4),
              &A[(size_t)(m0 + arow) * DD + ac4]);
        int kr = l >> 5, nv = (l & 31) * 4;
        cpa16(sb + (uint32_t)((GQ_B0 + kr * 136 + nv) * 4),
              &W[(size_t)kr * DD + n0 + nv]);
    }
    CP_COMMIT();

    for (int kc = 0; kc < 16; kc++) {
        CP_WAIT0();
        __syncthreads();
        if (kc < 15) {
            int k0n = (kc + 1) * 32;
            int ao = ((kc + 1) & 1) ? GQ_A1 : GQ_A0;
            int bo = ((kc + 1) & 1) ? GQ_B1 : GQ_B0;
            #pragma unroll
            for (int it = 0; it < 4; it++) {
                int l = tid + it * 256;
                int arow = l >> 3, ac4 = (l & 7) * 4;
                cpa16(sb + (uint32_t)((ao + arow * 36 + ac4) * 4),
                      &A[(size_t)(m0 + arow) * DD + k0n + ac4]);
                int kr = l >> 5, nv = (l & 31) * 4;
                cpa16(sb + (uint32_t)((bo + kr * 136 + nv) * 4),
                      &W[(size_t)(k0n + kr) * DD + n0 + nv]);
            }
            CP_COMMIT();
        }
        uint32_t ab_s = sb + (uint32_t)((((kc & 1) ? GQ_A1 : GQ_A0)) * 4);
        const uint32_t* Bb = sm + ((kc & 1) ? GQ_B1 : GQ_B0);
        #pragma unroll
        for (int kk = 0; kk < 32; kk += 8) {
            uint32_t a[4][4], b[4][2];
            #pragma unroll
            for (int im = 0; im < 4; im++)
                ldsm4(a[im][0], a[im][1], a[im][2], a[im][3],
                      ab_s + (uint32_t)(((wm + im * 16) * 36 + kk) * 4) + a_lane);
            #pragma unroll
            for (int in = 0; in < 4; in++) {
                int nb = wn + in * 8;
                b[in][0] = Bb[(kk + c) * 136 + nb + r];
                b[in][1] = Bb[(kk + c + 4) * 136 + nb + r];
            }
            #pragma unroll
            for (int im = 0; im < 4; im++)
                #pragma unroll
                for (int in = 0; in < 4; in++)
                    mma8(acc[im][in], a[im][0], a[im][1], a[im][2], a[im][3],
                         b[in][0], b[in][1]);
        }
    }

    #pragma unroll
    for (int im = 0; im < 4; im++) {
        #pragma unroll
        for (int in = 0; in < 4; in++) {
            int row0 = m0 + wm + im * 16 + r;
            int col0 = n0 + wn + in * 8 + 2 * c;
            float bz0 = bias[col0], bz1 = bias[col0 + 1];
            #pragma unroll
            for (int half = 0; half < 2; half++) {
                int row = row0 + half * 8;
                float2 v;
                v.x = acc[im][in][half * 2 + 0] + bz0;
                v.y = acc[im][in][half * 2 + 1] + bz1;
                if (round_split) {
                    v.x = tfr(v.x); v.y = tfr(v.y);
                    int bb = row >> 12, s = row & (SS - 1);
                    int h = col0 >> 6, dk = col0 & 63;
                    *reinterpret_cast<float2*>(
                        &C[(((size_t)(bb * HH + h)) * SS + s) * DK + dk]) = v;
                } else {
                    *reinterpret_cast<float2*>(&C[(size_t)row * DD + col0]) = v;
                }
            }
        }
    }
}

__global__ __launch_bounds__(256, 2) void gemm_qkv(
    const float* __restrict__ rin, const float* __restrict__ rw,
    const float* __restrict__ bq, const float* __restrict__ bk, const float* __restrict__ bv,
    float* __restrict__ cq, float* __restrict__ ck, float* __restrict__ cv)
{
    extern __shared__ uint32_t dsm[];
    int z = blockIdx.z;
    const float* A = rin + (size_t)z * MROWS * DD;
    const float* W = rw + (size_t)z * DD * DD;
    const float* bias = (z == 0) ? bq : (z == 1 ? bk : bv);
    float* C = (z == 0) ? cq : (z == 1 ? ck : cv);
    gemm_body_db(A, W, bias, C, 1, dsm);
}

__global__ __launch_bounds__(256, 2) void gemm_out(
    const float* __restrict__ A, const float* __restrict__ rw,
    const float* __restrict__ bias, float* __restrict__ C)
{
    extern __shared__ uint32_t dsm[];
    gemm_body_db(A, rw + (size_t)3 * DD * DD, bias, C, 0, dsm);
}

// ---------------------------------------------------------------------------
// Split-K single-pass flash attention.
// ---------------------------------------------------------------------------
#define FL_SMEM_WORDS (8704 + 2*4352 + 2*4608)
#define FL_SMEM_BYTES (FL_SMEM_WORDS * 4)
#define K0_OFF 8704
#define K1_OFF 13056
#define V0_OFF 17408
#define V1_OFF 22016

__global__ __launch_bounds__(256, 2) void flash_attn(
    const float* __restrict__ q, const float* __restrict__ k,
    const float* __restrict__ v, float* __restrict__ ctx,
    float* __restrict__ gm, float* __restrict__ glinv,
    float* __restrict__ opart, float* __restrict__ mpart, float* __restrict__ lpart)
{
    extern __shared__ uint32_t smem[];
    uint32_t sb = (uint32_t)__cvta_generic_to_shared(smem);
    int tid = threadIdx.x;
    int lane = tid & 31, wq = tid >> 5;
    int r = lane >> 2, c = lane & 3;
    int ag = lane >> 3, ar = lane & 7;

    int f = 79 - (int)blockIdx.x;
    int by, ch, nch;
    if (f < 8)       { by = f;              ch = 0;     nch = 1; }
    else if (f < 24) { int t = f - 8;  by = 8  + (t >> 1); ch = t & 1; nch = 2; }
    else if (f < 48) { int t = f - 24; by = 16 + t / 3;    ch = t % 3; nch = 3; }
    else             { int t = f - 48; by = 24 + (t >> 2); ch = t & 3; nch = 4; }
    int bh = blockIdx.y;
    int ktot = 2 * by + 2;
    int kt0 = ch * ktot / nch;
    int kt1 = (ch + 1) * ktot / nch;
    int nt = kt1 - kt0;

    const float* qb = q + (size_t)bh * SS * DK;
    const float* kb = k + (size_t)bh * SS * DK;
    const float* vb = v + (size_t)bh * SS * DK;

    int i0 = by * 128 + wq * 16 + r, i1 = i0 + 8;

    uint32_t qaddr = sb + (((wq * 16 + ar + ((ag & 1) << 3)) * 68 + ((ag >> 1) << 2)) << 2);
    uint32_t koff_l = ((((ag >> 1) << 3) + ar) * 68 + ((ag & 1) << 2)) << 2;

    #pragma unroll
    for (int l = tid; l < 2048; l += 256) {
        int rr = l >> 4, c4 = (l & 15) * 4;
        cpa16(sb + (rr * 68 + c4) * 4, &qb[(size_t)(by * 128 + rr) * DK + c4]);
    }
    {
        int kt = kt0;
        #pragma unroll
        for (int l = tid; l < 1024; l += 256) {
            int rr = l >> 4, c4 = (l & 15) * 4;
            cpa16(sb + (K0_OFF + rr * 68 + c4) * 4, &kb[(size_t)(kt * 64 + rr) * DK + c4]);
            cpa16(sb + (V0_OFF + rr * 72 + c4) * 4, &vb[(size_t)(kt * 64 + rr) * DK + c4]);
        }
    }
    CP_COMMIT();

    float m0 = -1e30f, m1 = -1e30f, l0 = 0.f, l1 = 0.f;
    float o[8][4];
    #pragma unroll
    for (int n = 0; n < 8; n++)
        #pragma unroll
        for (int qq = 0; qq < 4; qq++) o[n][qq] = 0.f;

    int sq1 = (lane & 28) | (c >> 1);
    int sq2 = sq1 + 2;
    int comp = c & 1;

    for (int t = 0; t < nt; t++) {
        CP_WAIT0();
        __syncthreads();
        if (t + 1 < nt) {
            int kt = kt0 + t + 1;
            int koffs = ((t + 1) & 1) ? K1_OFF : K0_OFF;
            int voffs = ((t + 1) & 1) ? V1_OFF : V0_OFF;
            #pragma unroll
            for (int l = tid; l < 1024; l += 256) {
                int rr = l >> 4, c4 = (l & 15) * 4;
                cpa16(sb + (koffs + rr * 68 + c4) * 4, &kb[(size_t)(kt * 64 + rr) * DK + c4]);
                cpa16(sb + (voffs + rr * 72 + c4) * 4, &vb[(size_t)(kt * 64 + rr) * DK + c4]);
            }
            CP_COMMIT();
        }

        int kt = kt0 + t;
        uint32_t kb_b = sb + ((t & 1) ? K1_OFF : K0_OFF) * 4;
        const uint32_t* Vb = smem + ((t & 1) ? V1_OFF : V0_OFF);

        float s[8][4];
        #pragma unroll
        for (int n = 0; n < 8; n++)
            #pragma unroll
            for (int qq = 0; qq < 4; qq++) s[n][qq] = 0.f;
        #pragma unroll
        for (int kk8 = 0; kk8 < 8; kk8++) {
            uint32_t a0, a1, a2, a3;
            ldsm4(a0, a1, a2, a3, qaddr + kk8 * 32);
            uint32_t b[8][2];
            #pragma unroll
            for (int p = 0; p < 4; p++)
                ldsm4(b[2*p][0], b[2*p][1], b[2*p+1][0], b[2*p+1][1],
                      kb_b + p * 4352 + koff_l + kk8 * 32);
            #pragma unroll
            for (int n = 0; n < 8; n++)
                mma8(s[n], a0, a1, a2, a3, b[n][0], b[n][1]);
        }

        bool diag = (kt >= 2 * by);
        float mx0 = -1e30f, mx1 = -1e30f;
        #pragma unroll
        for (int n = 0; n < 8; n++) {
            int j0 = kt * 64 + n * 8 + 2 * c;
            float t0 = s[n][0] * SCL, t1 = s[n][1] * SCL;
            float t2 = s[n][2] * SCL, t3 = s[n][3] * SCL;
            if (diag) {
                if (j0     > i0) t0 = -1e30f;
                if (j0 + 1 > i0) t1 = -1e30f;
                if (j0     > i1) t2 = -1e30f;
                if (j0 + 1 > i1) t3 = -1e30f;
            }
            s[n][0] = t0; s[n][1] = t1; s[n][2] = t2; s[n][3] = t3;
            mx0 = fmaxf(mx0, fmaxf(t0, t1));
            mx1 = fmaxf(mx1, fmaxf(t2, t3));
        }
        mx0 = fmaxf(mx0, __shfl_xor_sync(0xffffffffu, mx0, 1));
        mx0 = fmaxf(mx0, __shfl_xor_sync(0xffffffffu, mx0, 2));
        mx1 = fmaxf(mx1, __shfl_xor_sync(0xffffffffu, mx1, 1));
        mx1 = fmaxf(mx1, __shfl_xor_sync(0xffffffffu, mx1, 2));
        float mn0 = fmaxf(m0, mx0), mn1 = fmaxf(m1, mx1);
        float f0 = ex2(m0 - mn0), f1 = ex2(m1 - mn1);

        uint32_t pt[8][4];
        float sum0 = 0.f, sum1 = 0.f;
        #pragma unroll
        for (int n = 0; n < 8; n++) {
            float p0 = ex2(s[n][0] - mn0);
            float p1 = ex2(s[n][1] - mn0);
            float p2 = ex2(s[n][2] - mn1);
            float p3 = ex2(s[n][3] - mn1);
            sum0 += p0 + p1; sum1 += p2 + p3;
            pt[n][0] = f2tf(p0); pt[n][1] = f2tf(p1);
            pt[n][2] = f2tf(p2); pt[n][3] = f2tf(p3);
        }
        sum0 += __shfl_xor_sync(0xffffffffu, sum0, 1);
        sum0 += __shfl_xor_sync(0xffffffffu, sum0, 2);
        sum1 += __shfl_xor_sync(0xffffffffu, sum1, 1);
        sum1 += __shfl_xor_sync(0xffffffffu, sum1, 2);
        l0 = l0 * f0 + sum0; m0 = mn0;
        l1 = l1 * f1 + sum1; m1 = mn1;

        #pragma unroll
        for (int n = 0; n < 8; n++) {
            o[n][0] *= f0; o[n][1] *= f0;
            o[n][2] *= f1; o[n][3] *= f1;
        }

        #pragma unroll
        for (int g = 0; g < 8; g++) {
            uint32_t v0, v1, a0, a1, a2, a3;
            v0 = __shfl_sync(0xffffffffu, pt[g][0], sq1);
            v1 = __shfl_sync(0xffffffffu, pt[g][1], sq1);
            a0 = comp ? v1 : v0;
            v0 = __shfl_sync(0xffffffffu, pt[g][2], sq1);
            v1 = __shfl_sync(0xffffffffu, pt[g][3], sq1);
            a1 = comp ? v1 : v0;
            v0 = __shfl_sync(0xffffffffu, pt[g][0], sq2);
            v1 = __shfl_sync(0xffffffffu, pt[g][1], sq2);
            a2 = comp ? v1 : v0;
            v0 = __shfl_sync(0xffffffffu, pt[g][2], sq2);
            v1 = __shfl_sync(0xffffffffu, pt[g][3], sq2);
            a3 = comp ? v1 : v0;
            int kk = g * 8;
            #pragma unroll
            for (int n = 0; n < 8; n++) {
                uint32_t b0 = Vb[(kk + c) * 72 + n * 8 + r];
                uint32_t b1 = Vb[(kk + c + 4) * 72 + n * 8 + r];
                mma8(o[n], a0, a1, a2, a3, b0, b1);
            }
        }
    }

    if (nch == 1) {
        float inv0 = 1.0f / l0, inv1 = 1.0f / l1;
        if (c == 0) {
            gm[(size_t)bh * SS + i0] = m0;  glinv[(size_t)bh * SS + i0] = inv0;
            gm[(size_t)bh * SS + i1] = m1;  glinv[(size_t)bh * SS + i1] = inv1;
        }
        int bb = bh >> 3, h = bh & 7;
        #pragma unroll
        for (int n = 0; n < 8; n++) {
            int dk = n * 8 + 2 * c;
            float2 w0 = { tfr(o[n][0] * inv0), tfr(o[n][1] * inv0) };
            float2 w1 = { tfr(o[n][2] * inv1), tfr(o[n][3] * inv1) };
            *reinterpret_cast<float2*>(&ctx[((size_t)(bb * SS + i0)) * DD + h * 64 + dk]) = w0;
            *reinterpret_cast<float2*>(&ctx[((size_t)(bb * SS + i1)) * DD + h * 64 + dk]) = w1;
        }
    } else {
        size_t pidx = ((size_t)(bh * 32 + by)) * 4 + ch;
        int lr0 = wq * 16 + r, lr1 = lr0 + 8;
        if (c == 0) {
            mpart[pidx * 128 + lr0] = m0;  lpart[pidx * 128 + lr0] = l0;
            mpart[pidx * 128 + lr1] = m1;  lpart[pidx * 128 + lr1] = l1;
        }
        float* ob = opart + (pidx * 128) * DK;
        #pragma unroll
        for (int n = 0; n < 8; n++) {
            int dk = n * 8 + 2 * c;
            float2 w0 = { o[n][0], o[n][1] };
            float2 w1 = { o[n][2], o[n][3] };
            *reinterpret_cast<float2*>(&ob[(size_t)lr0 * DK + dk]) = w0;
            *reinterpret_cast<float2*>(&ob[(size_t)lr1 * DK + dk]) = w1;
        }
    }
}

// ---------------------------------------------------------------------------
// Combine partial (m, l, O) chunks for by >= 8.
// ---------------------------------------------------------------------------
__global__ __launch_bounds__(256) void flash_combine(
    const float* __restrict__ opart, const float* __restrict__ mpart,
    const float* __restrict__ lpart, float* __restrict__ ctx,
    float* __restrict__ gm, float* __restrict__ glinv)
{
    int by = 8 + blockIdx.x;
    int bh = blockIdx.y;
    int nch = by / 8 + 1;
    int tid = threadIdx.x;
    int row = tid >> 1, half = tid & 1;
    size_t p0 = ((size_t)(bh * 32 + by)) * 4;

    float mf = -1e30f;
    #pragma unroll 4
    for (int chv = 0; chv < 4; chv++)
        if (chv < nch) mf = fmaxf(mf, mpart[(p0 + chv) * 128 + row]);
    float L = 0.f;
    float wch[4];
    #pragma unroll 4
    for (int chv = 0; chv < 4; chv++) {
        if (chv < nch) {
            float w = ex2(mpart[(p0 + chv) * 128 + row] - mf);
            wch[chv] = w;
            L += lpart[(p0 + chv) * 128 + row] * w;
        } else wch[chv] = 0.f;
    }
    float invL = 1.0f / L;

    float acc[32];
    #pragma unroll
    for (int j = 0; j < 32; j++) acc[j] = 0.f;
    #pragma unroll 4
    for (int chv = 0; chv < 4; chv++) {
        if (chv >= nch) break;
        const float* ob = opart + ((p0 + chv) * 128 + row) * DK + half * 32;
        float w = wch[chv];
        #pragma unroll
        for (int j4 = 0; j4 < 8; j4++) {
            float4 vv = *reinterpret_cast<const float4*>(&ob[j4 * 4]);
            acc[j4*4+0] += vv.x * w; acc[j4*4+1] += vv.y * w;
            acc[j4*4+2] += vv.z * w; acc[j4*4+3] += vv.w * w;
        }
    }

    int i = by * 128 + row;
    int bb = bh >> 3, h = bh & 7;
    float* cp = ctx + ((size_t)(bb * SS + i)) * DD + h * 64 + half * 32;
    #pragma unroll
    for (int j4 = 0; j4 < 8; j4++) {
        float4 vv = { tfr(acc[j4*4+0] * invL), tfr(acc[j4*4+1] * invL),
                      tfr(acc[j4*4+2] * invL), tfr(acc[j4*4+3] * invL) };
        *reinterpret_cast<float4*>(&cp[j4 * 4]) = vv;
    }
    if (half == 0) {
        gm[(size_t)bh * SS + i] = mf;
        glinv[(size_t)bh * SS + i] = invL;
    }
}

// ---------------------------------------------------------------------------
// attn writer: zero tiles above the diagonal; recompute S + softmax below.
// Stage normalized P in smem (stride 136), coalesced streaming stores.
// ---------------------------------------------------------------------------
#define AW_SMEM_WORDS (8704 * 2)
#define AW_SMEM_BYTES (AW_SMEM_WORDS * 4)

__global__ __launch_bounds__(256, 2) void attn_write(
    const float* __restrict__ q, const float* __restrict__ k,
    const float* __restrict__ gm, const float* __restrict__ glinv,
    float* __restrict__ attn)
{
    int bx = blockIdx.x, by = blockIdx.y, bh = blockIdx.z;
    float* ab = attn + (size_t)bh * SS * SS;
    int tid = threadIdx.x;

    if (bx > by) {  // zero tile
        float4 z = { 0.f, 0.f, 0.f, 0.f };
        #pragma unroll 4
        for (int l = tid; l < 4096; l += 256) {
            int rr = l >> 5, c4 = (l & 31) * 4;
            __stcs(reinterpret_cast<float4*>(
                &ab[(size_t)(by * 128 + rr) * SS + bx * 128 + c4]), z);
        }
        return;
    }

    extern __shared__ uint32_t sm2[];
    uint32_t* Qs = sm2;
    uint32_t* Ks = sm2 + 8704;
    const float* qb = q + (size_t)bh * SS * DK;
    const float* kb = k + (size_t)bh * SS * DK;

    int lane = tid & 31, warp = tid >> 5;
    int wm = (warp >> 2) * 64, wn = (warp & 3) * 32;
    int r = lane >> 2, c = lane & 3;

    // hoist per-row softmax stats out of the epilogue dependency chain
    float mh[4][2], lh[4][2];
    #pragma unroll
    for (int im = 0; im < 4; im++) {
        int i0 = by * 128 + wm + im * 16 + r;
        mh[im][0] = __ldg(&gm[(size_t)bh * SS + i0]);
        mh[im][1] = __ldg(&gm[(size_t)bh * SS + i0 + 8]);
        lh[im][0] = __ldg(&glinv[(size_t)bh * SS + i0]);
        lh[im][1] = __ldg(&glinv[(size_t)bh * SS + i0 + 8]);
    }

    #pragma unroll 4
    for (int l = tid; l < 2048; l += 256) {
        int rr = l >> 4, c4 = (l & 15) * 4;
        *reinterpret_cast<uint4*>(&Qs[rr * 68 + c4]) =
            *reinterpret_cast<const uint4*>(&qb[(size_t)(by * 128 + rr) * DK + c4]);
        *reinterpret_cast<uint4*>(&Ks[rr * 68 + c4]) =
            *reinterpret_cast<const uint4*>(&kb[(size_t)(bx * 128 + rr) * DK + c4]);
    }
    __syncthreads();

    float acc[4][4][4];
    #pragma unroll
    for (int im = 0; im < 4; im++)
        #pragma unroll
        for (int in = 0; in < 4; in++)
            #pragma unroll
            for (int qq = 0; qq < 4; qq++) acc[im][in][qq] = 0.f;

    #pragma unroll
    for (int kk = 0; kk < 64; kk += 8) {
        uint32_t a[4][4], b[4][2];
        #pragma unroll
        for (int im = 0; im < 4; im++) {
            int mb = wm + im * 16;
            a[im][0] = Qs[(mb + r) * 68 + kk + c];
            a[im][1] = Qs[(mb + r + 8) * 68 + kk + c];
            a[im][2] = Qs[(mb + r) * 68 + kk + c + 4];
            a[im][3] = Qs[(mb + r + 8) * 68 + kk + c + 4];
        }
        #pragma unroll
        for (int in = 0; in < 4; in++) {
            int nb = wn + in * 8;
            b[in][0] = Ks[(nb + r) * 68 + kk + c];
            b[in][1] = Ks[(nb + r) * 68 + kk + c + 4];
        }
        #pragma unroll
        for (int im = 0; im < 4; im++)
            #pragma unroll
            for (int in = 0; in < 4; in++)
                mma8(acc[im][in], a[im][0], a[im][1], a[im][2], a[im][3],
                     b[in][0], b[in][1]);
    }

    __syncthreads();  // everyone done reading Qs/Ks
    float* Ps = reinterpret_cast<float*>(sm2);
    bool dg = (bx == by);
    #pragma unroll
    for (int im = 0; im < 4; im++) {
        int i0 = by * 128 + wm + im * 16 + r;
        int i1 = i0 + 8;
        int lr0 = wm + im * 16 + r, lr1 = lr0 + 8;
        float m_0 = mh[im][0], li0 = lh[im][0];
        float m_1 = mh[im][1], li1 = lh[im][1];
        #pragma unroll
        for (int in = 0; in < 4; in++) {
            int j = wn + in * 8 + 2 * c;
            int j0 = bx * 128 + j;
            float p0 = ex2(acc[im][in][0] * SCL - m_0) * li0;
            float p1 = ex2(acc[im][in][1] * SCL - m_0) * li0;
            float p2 = ex2(acc[im][in][2] * SCL - m_1) * li1;
            float p3 = ex2(acc[im][in][3] * SCL - m_1) * li1;
            if (dg) {
                if (j0     > i0) p0 = 0.f;
                if (j0 + 1 > i0) p1 = 0.f;
                if (j0     > i1) p2 = 0.f;
                if (j0 + 1 > i1) p3 = 0.f;
            }
            float2 w01 = { p0, p1 };
            float2 w23 = { p2, p3 };
            *reinterpret_cast<float2*>(&Ps[lr0 * 136 + j]) = w01;
            *reinterpret_cast<float2*>(&Ps[lr1 * 136 + j]) = w23;
        }
    }
    __syncthreads();

    #pragma unroll 4
    for (int l = tid; l < 4096; l += 256) {
        int rr = l >> 5, c4 = (l & 31) * 4;
        float4 vv = *reinterpret_cast<const float4*>(&Ps[rr * 136 + c4]);
        __stcs(reinterpret_cast<float4*>(
            &ab[(size_t)(by * 128 + rr) * SS + bx * 128 + c4]), vv);
    }
}

// ---------------------------------------------------------------------------
extern "C" void kernel_launch(void* const* d_in, const int* in_sizes, int n_in,
                              void* d_out, int out_size)
{
    (void)in_sizes; (void)n_in;
    const float* Q  = (const float*)d_in[0];
    const float* K  = (const float*)d_in[1];
    const float* V  = (const float*)d_in[2];
    const float* wq = (const float*)d_in[3];
    const float* bq = (const float*)d_in[4];
    const float* wk = (const float*)d_in[5];
    const float* bk = (const float*)d_in[6];
    const float* wv = (const float*)d_in[7];
    const float* bv = (const float*)d_in[8];
    const float* wo = (const float*)d_in[9];
    const float* bo = (const float*)d_in[10];
    float* out = (float*)d_out;

    const size_t outN  = (size_t)MROWS * DD;
    const size_t attnN = (size_t)BH * SS * SS;

    int write_attn;
    float* attn;
    if ((size_t)out_size >= outN + attnN) {
        attn = out + outN;
        write_attn = 1;
    } else {
        void* p = nullptr;
        cudaGetSymbolAddress(&p, g_attn);
        attn = (float*)p;
        write_attn = 0;
    }

    float *qp, *kp, *vp, *ctxp, *mp, *lp, *op, *mpp, *lpp, *rin, *rw;
    { void* p; cudaGetSymbolAddress(&p, g_q);     qp   = (float*)p; }
    { void* p; cudaGetSymbolAddress(&p, g_k);     kp   = (float*)p; }
    { void* p; cudaGetSymbolAddress(&p, g_v);     vp   = (float*)p; }
    { void* p; cudaGetSymbolAddress(&p, g_ctx);   ctxp = (float*)p; }
    { void* p; cudaGetSymbolAddress(&p, g_m);     mp   = (float*)p; }
    { void* p; cudaGetSymbolAddress(&p, g_linv);  lp   = (float*)p; }
    { void* p; cudaGetSymbolAddress(&p, g_opart); op   = (float*)p; }
    { void* p; cudaGetSymbolAddress(&p, g_mpart); mpp  = (float*)p; }
    { void* p; cudaGetSymbolAddress(&p, g_lpart); lpp  = (float*)p; }
    { void* p; cudaGetSymbolAddress(&p, g_rin);   rin  = (float*)p; }
    { void* p; cudaGetSymbolAddress(&p, g_rw);    rw   = (float*)p; }

    cudaFuncSetAttribute(flash_attn, cudaFuncAttributeMaxDynamicSharedMemorySize,
                         FL_SMEM_BYTES);
    cudaFuncSetAttribute(attn_write, cudaFuncAttributeMaxDynamicSharedMemorySize,
                         AW_SMEM_BYTES);
    cudaFuncSetAttribute(gemm_qkv, cudaFuncAttributeMaxDynamicSharedMemorySize,
                         GEMM_SMEM_BYTES);
    cudaFuncSetAttribute(gemm_out, cudaFuncAttributeMaxDynamicSharedMemorySize,
                         GEMM_SMEM_BYTES);

    dim3 blk(256);
    size_t totalRound = (NINW + NWW) / 4;
    dim3 gQKV(DD / 128, MROWS / 128, 3);
    dim3 gFA(80, BH);
    dim3 gCB(24, BH);
    dim3 gOut(DD / 128, MROWS / 128);

    // Sequential main chain (known-good R11 ordering)
    round_pre<<<(unsigned)(totalRound / 256), blk>>>(Q, K, V, wq, wk, wv, wo, rin, rw);
    gemm_qkv<<<gQKV, blk, GEMM_SMEM_BYTES>>>(rin, rw, bq, bk, bv, qp, kp, vp);
    flash_attn<<<gFA, blk, FL_SMEM_BYTES>>>(qp, kp, vp, ctxp, mp, lp, op, mpp, lpp);
    flash_combine<<<gCB, blk>>>(op, mpp, lpp, ctxp, mp, lp);

    if (write_attn) {
        // Fork ONLY the small tensor-bound gemm_out beside the DRAM-bound attn_write.
        cudaStream_t s2;
        cudaStreamCreate(&s2);
        cudaEvent_t eB, eC;
        cudaEventCreateWithFlags(&eB, cudaEventDisableTiming);
        cudaEventCreateWithFlags(&eC, cudaEventDisableTiming);

        cudaEventRecord(eB, 0);
        cudaStreamWaitEvent(s2, eB, 0);
        gemm_out<<<gOut, blk, GEMM_SMEM_BYTES, s2>>>(ctxp, rw, bo, out);
        cudaEventRecord(eC, s2);

        dim3 gAW(SS / 128, SS / 128, BH);
        attn_write<<<gAW, blk, AW_SMEM_BYTES>>>(qp, kp, mp, lp, attn);

        cudaStreamWaitEvent(0, eC, 0);
    } else {
        gemm_out<<<gOut, blk, GEMM_SMEM_BYTES>>>(ctxp, rw, bo, out);
    }
}

// round 15
// speedup vs baseline: 1.0623x; 1.0162x over previous
#include <cuda_runtime.h>
#include <cuda_bf16.h>
#include <cstdint>

#define BB 2
#define SS 4096
#define DD 512
#define HH 8
#define DK 64
#define BH (BB*HH)          // 16
#define MROWS (BB*SS)       // 8192

// log2(e) * 0.125 (softmax scale folded into base-2 domain)
#define SCL 0.18033688011112042f

// Scratch (device globals: allocation-free)
__device__ float g_q[(size_t)BH * SS * DK];
__device__ float g_k[(size_t)BH * SS * DK];
__device__ float g_v[(size_t)BH * SS * DK];
__device__ float g_ctx[(size_t)MROWS * DD];
__device__ float g_m[(size_t)BH * SS];
__device__ float g_linv[(size_t)BH * SS];
__device__ float g_opart[(size_t)BH * 32 * 4 * 128 * DK];
__device__ float g_mpart[(size_t)BH * 32 * 4 * 128];
__device__ float g_lpart[(size_t)BH * 32 * 4 * 128];
__device__ float g_rin[(size_t)3 * MROWS * DD];     // tf32-rounded Q,K,V inputs
__device__ float g_rw[(size_t)4 * DD * DD];         // tf32-rounded weights
__device__ float g_attn[(size_t)BH * SS * SS];      // used only if attn not in d_out

// ---------------------------------------------------------------------------
__device__ __forceinline__ uint32_t f2tf(float x) {
    uint32_t u;
    asm("cvt.rna.tf32.f32 %0, %1;" : "=r"(u) : "f"(x));
    return u;
}
__device__ __forceinline__ float tfr(float x) {
    return __uint_as_float(f2tf(x));
}
__device__ __forceinline__ float ex2(float x) {
    float y;
    asm("ex2.approx.ftz.f32 %0, %1;" : "=f"(y) : "f"(x));
    return y;
}
__device__ __forceinline__ void mma8(float* d,
    uint32_t a0, uint32_t a1, uint32_t a2, uint32_t a3,
    uint32_t b0, uint32_t b1)
{
    asm volatile(
        "mma.sync.aligned.m16n8k8.row.col.f32.tf32.tf32.f32 "
        "{%0,%1,%2,%3},{%4,%5,%6,%7},{%8,%9},{%0,%1,%2,%3};"
        : "+f"(d[0]), "+f"(d[1]), "+f"(d[2]), "+f"(d[3])
        : "r"(a0), "r"(a1), "r"(a2), "r"(a3), "r"(b0), "r"(b1));
}
__device__ __forceinline__ void ldsm4(uint32_t& r0, uint32_t& r1,
                                      uint32_t& r2, uint32_t& r3, uint32_t addr)
{
    asm volatile("ldmatrix.sync.aligned.m8n8.x4.shared.b16 {%0,%1,%2,%3}, [%4];"
        : "=r"(r0), "=r"(r1), "=r"(r2), "=r"(r3) : "r"(addr));
}
__device__ __forceinline__ void cpa16(uint32_t dst, const void* src) {
    asm volatile("cp.async.cg.shared.global [%0], [%1], 16;" :: "r"(dst), "l"(src));
}
#define CP_COMMIT() asm volatile("cp.async.commit_group;")
#define CP_WAIT0()  asm volatile("cp.async.wait_group 0;")

// ---------------------------------------------------------------------------
// Prepass: tf32-round Q,K,V inputs and the 4 weight matrices into scratch.
// ---------------------------------------------------------------------------
#define NINW ((size_t)3 * MROWS * DD)    // 12,582,912 floats
#define NWW  ((size_t)4 * DD * DD)       // 1,048,576 floats

__global__ __launch_bounds__(256) void round_pre(
    const float* __restrict__ Q, const float* __restrict__ K, const float* __restrict__ V,
    const float* __restrict__ wq, const float* __restrict__ wk,
    const float* __restrict__ wv, const float* __restrict__ wo,
    float* __restrict__ rin, float* __restrict__ rw)
{
    size_t idx = ((size_t)blockIdx.x * 256 + threadIdx.x) * 4;
    const size_t NPER = (size_t)MROWS * DD;   // 4,194,304
    if (idx < NINW) {
        const float* src = (idx < NPER) ? Q : (idx < 2 * NPER ? K : V);
        size_t off = idx & (NPER - 1);
        float4 v = *reinterpret_cast<const float4*>(&src[off]);
        float4 o = { tfr(v.x), tfr(v.y), tfr(v.z), tfr(v.w) };
        *reinterpret_cast<float4*>(&rin[idx]) = o;
    } else {
        size_t j = idx - NINW;
        const size_t WPER = (size_t)DD * DD;  // 262,144
        const float* src = (j < WPER) ? wq : (j < 2 * WPER ? wk : (j < 3 * WPER ? wv : wo));
        size_t off = j & (WPER - 1);
        float4 v = *reinterpret_cast<const float4*>(&src[off]);
        float4 o = { tfr(v.x), tfr(v.y), tfr(v.z), tfr(v.w) };
        *reinterpret_cast<float4*>(&rw[j]) = o;
    }
}

// ---------------------------------------------------------------------------
// Double-buffered TF32 GEMM: C[M x 512] = A[M x 512] @ W[512 x 512] + bias.
// smem (dynamic): A0[128*36] A1 | B0[32*136] B1  = 17920 words
// ---------------------------------------------------------------------------
#define GQ_A0 0
#define GQ_A1 4608
#define GQ_B0 9216
#define GQ_B1 13568
#define GEMM_SMEM_BYTES (17920 * 4)   // 71680

__device__ __forceinline__ void gemm_body_db(
    const float* __restrict__ A, const float* __restrict__ W,
    const float* __restrict__ bias, float* __restrict__ C,
    int round_split, uint32_t* sm)
{
    uint32_t sb = (uint32_t)__cvta_generic_to_shared(sm);
    int tid = threadIdx.x;
    int lane = tid & 31, warp = tid >> 5;
    int wm = (warp >> 2) * 64, wn = (warp & 3) * 32;
    int r = lane >> 2, c = lane & 3;
    int ag = lane >> 3, ar = lane & 7;
    int m0 = blockIdx.y * 128, n0 = blockIdx.x * 128;
    uint32_t a_lane = ((uint32_t)((ar + ((ag & 1) << 3)) * 36 + ((ag >> 1) << 2))) << 2;

    float acc[4][4][4] = {};

    #pragma unroll
    for (int it = 0; it < 4; it++) {
        int l = tid + it * 256;
        int arow = l >> 3, ac4 = (l & 7) * 4;
        cpa16(sb + (uint32_t)((GQ_A0 + arow * 36 + ac4) * 4),
              &A[(size_t)(m0 + arow) * DD + ac4]);
        int kr = l >> 5, nv = (l & 31) * 4;
        cpa16(sb + (uint32_t)((GQ_B0 + kr * 136 + nv) * 4),
              &W[(size_t)kr * DD + n0 + nv]);
    }
    CP_COMMIT();

    for (int kc = 0; kc < 16; kc++) {
        CP_WAIT0();
        __syncthreads();
        if (kc < 15) {
            int k0n = (kc + 1) * 32;
            int ao = ((kc + 1) & 1) ? GQ_A1 : GQ_A0;
            int bo = ((kc + 1) & 1) ? GQ_B1 : GQ_B0;
            #pragma unroll
            for (int it = 0; it < 4; it++) {
                int l = tid + it * 256;
                int arow = l >> 3, ac4 = (l & 7) * 4;
                cpa16(sb + (uint32_t)((ao + arow * 36 + ac4) * 4),
                      &A[(size_t)(m0 + arow) * DD + k0n + ac4]);
                int kr = l >> 5, nv = (l & 31) * 4;
                cpa16(sb + (uint32_t)((bo + kr * 136 + nv) * 4),
                      &W[(size_t)(k0n + kr) * DD + n0 + nv]);
            }
            CP_COMMIT();
        }
        uint32_t ab_s = sb + (uint32_t)((((kc & 1) ? GQ_A1 : GQ_A0)) * 4);
        const uint32_t* Bb = sm + ((kc & 1) ? GQ_B1 : GQ_B0);
        #pragma unroll
        for (int kk = 0; kk < 32; kk += 8) {
            uint32_t a[4][4], b[4][2];
            #pragma unroll
            for (int im = 0; im < 4; im++)
                ldsm4(a[im][0], a[im][1], a[im][2], a[im][3],
                      ab_s + (uint32_t)(((wm + im * 16) * 36 + kk) * 4) + a_lane);
            #pragma unroll
            for (int in = 0; in < 4; in++) {
                int nb = wn + in * 8;
                b[in][0] = Bb[(kk + c) * 136 + nb + r];
                b[in][1] = Bb[(kk + c + 4) * 136 + nb + r];
            }
            #pragma unroll
            for (int im = 0; im < 4; im++)
                #pragma unroll
                for (int in = 0; in < 4; in++)
                    mma8(acc[im][in], a[im][0], a[im][1], a[im][2], a[im][3],
                         b[in][0], b[in][1]);
        }
    }

    #pragma unroll
    for (int im = 0; im < 4; im++) {
        #pragma unroll
        for (int in = 0; in < 4; in++) {
            int row0 = m0 + wm + im * 16 + r;
            int col0 = n0 + wn + in * 8 + 2 * c;
            float bz0 = bias[col0], bz1 = bias[col0 + 1];
            #pragma unroll
            for (int half = 0; half < 2; half++) {
                int row = row0 + half * 8;
                float2 v;
                v.x = acc[im][in][half * 2 + 0] + bz0;
                v.y = acc[im][in][half * 2 + 1] + bz1;
                if (round_split) {
                    v.x = tfr(v.x); v.y = tfr(v.y);
                    int bb = row >> 12, s = row & (SS - 1);
                    int h = col0 >> 6, dk = col0 & 63;
                    *reinterpret_cast<float2*>(
                        &C[(((size_t)(bb * HH + h)) * SS + s) * DK + dk]) = v;
                } else {
                    *reinterpret_cast<float2*>(&C[(size_t)row * DD + col0]) = v;
                }
            }
        }
    }
}

__global__ __launch_bounds__(256, 2) void gemm_qkv(
    const float* __restrict__ rin, const float* __restrict__ rw,
    const float* __restrict__ bq, const float* __restrict__ bk, const float* __restrict__ bv,
    float* __restrict__ cq, float* __restrict__ ck, float* __restrict__ cv)
{
    extern __shared__ uint32_t dsm[];
    int z = blockIdx.z;
    const float* A = rin + (size_t)z * MROWS * DD;
    const float* W = rw + (size_t)z * DD * DD;
    const float* bias = (z == 0) ? bq : (z == 1 ? bk : bv);
    float* C = (z == 0) ? cq : (z == 1 ? ck : cv);
    gemm_body_db(A, W, bias, C, 1, dsm);
}

__global__ __launch_bounds__(256, 2) void gemm_out(
    const float* __restrict__ A, const float* __restrict__ rw,
    const float* __restrict__ bias, float* __restrict__ C)
{
    extern __shared__ uint32_t dsm[];
    gemm_body_db(A, rw + (size_t)3 * DD * DD, bias, C, 0, dsm);
}

// ---------------------------------------------------------------------------
// Split-K single-pass flash attention.
// ---------------------------------------------------------------------------
#define FL_SMEM_WORDS (8704 + 2*4352 + 2*4608)
#define FL_SMEM_BYTES (FL_SMEM_WORDS * 4)
#define K0_OFF 8704
#define K1_OFF 13056
#define V0_OFF 17408
#define V1_OFF 22016

__global__ __launch_bounds__(256, 2) void flash_attn(
    const float* __restrict__ q, const float* __restrict__ k,
    const float* __restrict__ v, float* __restrict__ ctx,
    float* __restrict__ gm, float* __restrict__ glinv,
    float* __restrict__ opart, float* __restrict__ mpart, float* __restrict__ lpart)
{
    extern __shared__ uint32_t smem[];
    uint32_t sb = (uint32_t)__cvta_generic_to_shared(smem);
    int tid = threadIdx.x;
    int lane = tid & 31, wq = tid >> 5;
    int r = lane >> 2, c = lane & 3;
    int ag = lane >> 3, ar = lane & 7;

    int f = 79 - (int)blockIdx.x;
    int by, ch, nch;
    if (f < 8)       { by = f;              ch = 0;     nch = 1; }
    else if (f < 24) { int t = f - 8;  by = 8  + (t >> 1); ch = t & 1; nch = 2; }
    else if (f < 48) { int t = f - 24; by = 16 + t / 3;    ch = t % 3; nch = 3; }
    else             { int t = f - 48; by = 24 + (t >> 2); ch = t & 3; nch = 4; }
    int bh = blockIdx.y;
    int ktot = 2 * by + 2;
    int kt0 = ch * ktot / nch;
    int kt1 = (ch + 1) * ktot / nch;
    int nt = kt1 - kt0;

    const float* qb = q + (size_t)bh * SS * DK;
    const float* kb = k + (size_t)bh * SS * DK;
    const float* vb = v + (size_t)bh * SS * DK;

    int i0 = by * 128 + wq * 16 + r, i1 = i0 + 8;

    uint32_t qaddr = sb + (((wq * 16 + ar + ((ag & 1) << 3)) * 68 + ((ag >> 1) << 2)) << 2);
    uint32_t koff_l = ((((ag >> 1) << 3) + ar) * 68 + ((ag & 1) << 2)) << 2;

    #pragma unroll
    for (int l = tid; l < 2048; l += 256) {
        int rr = l >> 4, c4 = (l & 15) * 4;
        cpa16(sb + (rr * 68 + c4) * 4, &qb[(size_t)(by * 128 + rr) * DK + c4]);
    }
    {
        int kt = kt0;
        #pragma unroll
        for (int l = tid; l < 1024; l += 256) {
            int rr = l >> 4, c4 = (l & 15) * 4;
            cpa16(sb + (K0_OFF + rr * 68 + c4) * 4, &kb[(size_t)(kt * 64 + rr) * DK + c4]);
            cpa16(sb + (V0_OFF + rr * 72 + c4) * 4, &vb[(size_t)(kt * 64 + rr) * DK + c4]);
        }
    }
    CP_COMMIT();

    float m0 = -1e30f, m1 = -1e30f, l0 = 0.f, l1 = 0.f;
    float o[8][4];
    #pragma unroll
    for (int n = 0; n < 8; n++)
        #pragma unroll
        for (int qq = 0; qq < 4; qq++) o[n][qq] = 0.f;

    int sq1 = (lane & 28) | (c >> 1);
    int sq2 = sq1 + 2;
    int comp = c & 1;

    for (int t = 0; t < nt; t++) {
        CP_WAIT0();
        __syncthreads();
        if (t + 1 < nt) {
            int kt = kt0 + t + 1;
            int koffs = ((t + 1) & 1) ? K1_OFF : K0_OFF;
            int voffs = ((t + 1) & 1) ? V1_OFF : V0_OFF;
            #pragma unroll
            for (int l = tid; l < 1024; l += 256) {
                int rr = l >> 4, c4 = (l & 15) * 4;
                cpa16(sb + (koffs + rr * 68 + c4) * 4, &kb[(size_t)(kt * 64 + rr) * DK + c4]);
                cpa16(sb + (voffs + rr * 72 + c4) * 4, &vb[(size_t)(kt * 64 + rr) * DK + c4]);
            }
            CP_COMMIT();
        }

        int kt = kt0 + t;
        uint32_t kb_b = sb + ((t & 1) ? K1_OFF : K0_OFF) * 4;
        const uint32_t* Vb = smem + ((t & 1) ? V1_OFF : V0_OFF);

        float s[8][4];
        #pragma unroll
        for (int n = 0; n < 8; n++)
            #pragma unroll
            for (int qq = 0; qq < 4; qq++) s[n][qq] = 0.f;
        #pragma unroll
        for (int kk8 = 0; kk8 < 8; kk8++) {
            uint32_t a0, a1, a2, a3;
            ldsm4(a0, a1, a2, a3, qaddr + kk8 * 32);
            uint32_t b[8][2];
            #pragma unroll
            for (int p = 0; p < 4; p++)
                ldsm4(b[2*p][0], b[2*p][1], b[2*p+1][0], b[2*p+1][1],
                      kb_b + p * 4352 + koff_l + kk8 * 32);
            #pragma unroll
            for (int n = 0; n < 8; n++)
                mma8(s[n], a0, a1, a2, a3, b[n][0], b[n][1]);
        }

        bool diag = (kt >= 2 * by);
        float mx0 = -1e30f, mx1 = -1e30f;
        #pragma unroll
        for (int n = 0; n < 8; n++) {
            int j0 = kt * 64 + n * 8 + 2 * c;
            float t0 = s[n][0] * SCL, t1 = s[n][1] * SCL;
            float t2 = s[n][2] * SCL, t3 = s[n][3] * SCL;
            if (diag) {
                if (j0     > i0) t0 = -1e30f;
                if (j0 + 1 > i0) t1 = -1e30f;
                if (j0     > i1) t2 = -1e30f;
                if (j0 + 1 > i1) t3 = -1e30f;
            }
            s[n][0] = t0; s[n][1] = t1; s[n][2] = t2; s[n][3] = t3;
            mx0 = fmaxf(mx0, fmaxf(t0, t1));
            mx1 = fmaxf(mx1, fmaxf(t2, t3));
        }
        mx0 = fmaxf(mx0, __shfl_xor_sync(0xffffffffu, mx0, 1));
        mx0 = fmaxf(mx0, __shfl_xor_sync(0xffffffffu, mx0, 2));
        mx1 = fmaxf(mx1, __shfl_xor_sync(0xffffffffu, mx1, 1));
        mx1 = fmaxf(mx1, __shfl_xor_sync(0xffffffffu, mx1, 2));
        float mn0 = fmaxf(m0, mx0), mn1 = fmaxf(m1, mx1);
        float f0 = ex2(m0 - mn0), f1 = ex2(m1 - mn1);

        uint32_t pt[8][4];
        float sum0 = 0.f, sum1 = 0.f;
        #pragma unroll
        for (int n = 0; n < 8; n++) {
            float p0 = ex2(s[n][0] - mn0);
            float p1 = ex2(s[n][1] - mn0);
            float p2 = ex2(s[n][2] - mn1);
            float p3 = ex2(s[n][3] - mn1);
            sum0 += p0 + p1; sum1 += p2 + p3;
            pt[n][0] = f2tf(p0); pt[n][1] = f2tf(p1);
            pt[n][2] = f2tf(p2); pt[n][3] = f2tf(p3);
        }
        sum0 += __shfl_xor_sync(0xffffffffu, sum0, 1);
        sum0 += __shfl_xor_sync(0xffffffffu, sum0, 2);
        sum1 += __shfl_xor_sync(0xffffffffu, sum1, 1);
        sum1 += __shfl_xor_sync(0xffffffffu, sum1, 2);
        l0 = l0 * f0 + sum0; m0 = mn0;
        l1 = l1 * f1 + sum1; m1 = mn1;

        #pragma unroll
        for (int n = 0; n < 8; n++) {
            o[n][0] *= f0; o[n][1] *= f0;
            o[n][2] *= f1; o[n][3] *= f1;
        }

        #pragma unroll
        for (int g = 0; g < 8; g++) {
            uint32_t v0, v1, a0, a1, a2, a3;
            v0 = __shfl_sync(0xffffffffu, pt[g][0], sq1);
            v1 = __shfl_sync(0xffffffffu, pt[g][1], sq1);
            a0 = comp ? v1 : v0;
            v0 = __shfl_sync(0xffffffffu, pt[g][2], sq1);
            v1 = __shfl_sync(0xffffffffu, pt[g][3], sq1);
            a1 = comp ? v1 : v0;
            v0 = __shfl_sync(0xffffffffu, pt[g][0], sq2);
            v1 = __shfl_sync(0xffffffffu, pt[g][1], sq2);
            a2 = comp ? v1 : v0;
            v0 = __shfl_sync(0xffffffffu, pt[g][2], sq2);
            v1 = __shfl_sync(0xffffffffu, pt[g][3], sq2);
            a3 = comp ? v1 : v0;
            int kk = g * 8;
            #pragma unroll
            for (int n = 0; n < 8; n++) {
                uint32_t b0 = Vb[(kk + c) * 72 + n * 8 + r];
                uint32_t b1 = Vb[(kk + c + 4) * 72 + n * 8 + r];
                mma8(o[n], a0, a1, a2, a3, b0, b1);
            }
        }
    }

    if (nch == 1) {
        float inv0 = 1.0f / l0, inv1 = 1.0f / l1;
        if (c == 0) {
            gm[(size_t)bh * SS + i0] = m0;  glinv[(size_t)bh * SS + i0] = inv0;
            gm[(size_t)bh * SS + i1] = m1;  glinv[(size_t)bh * SS + i1] = inv1;
        }
        int bb = bh >> 3, h = bh & 7;
        #pragma unroll
        for (int n = 0; n < 8; n++) {
            int dk = n * 8 + 2 * c;
            float2 w0 = { tfr(o[n][0] * inv0), tfr(o[n][1] * inv0) };
            float2 w1 = { tfr(o[n][2] * inv1), tfr(o[n][3] * inv1) };
            *reinterpret_cast<float2*>(&ctx[((size_t)(bb * SS + i0)) * DD + h * 64 + dk]) = w0;
            *reinterpret_cast<float2*>(&ctx[((size_t)(bb * SS + i1)) * DD + h * 64 + dk]) = w1;
        }
    } else {
        size_t pidx = ((size_t)(bh * 32 + by)) * 4 + ch;
        int lr0 = wq * 16 + r, lr1 = lr0 + 8;
        if (c == 0) {
            mpart[pidx * 128 + lr0] = m0;  lpart[pidx * 128 + lr0] = l0;
            mpart[pidx * 128 + lr1] = m1;  lpart[pidx * 128 + lr1] = l1;
        }
        float* ob = opart + (pidx * 128) * DK;
        #pragma unroll
        for (int n = 0; n < 8; n++) {
            int dk = n * 8 + 2 * c;
            float2 w0 = { o[n][0], o[n][1] };
            float2 w1 = { o[n][2], o[n][3] };
            *reinterpret_cast<float2*>(&ob[(size_t)lr0 * DK + dk]) = w0;
            *reinterpret_cast<float2*>(&ob[(size_t)lr1 * DK + dk]) = w1;
        }
    }
}

// ---------------------------------------------------------------------------
// Combine partial (m, l, O) chunks for by >= 8.
// ---------------------------------------------------------------------------
__global__ __launch_bounds__(256) void flash_combine(
    const float* __restrict__ opart, const float* __restrict__ mpart,
    const float* __restrict__ lpart, float* __restrict__ ctx,
    float* __restrict__ gm, float* __restrict__ glinv)
{
    int by = 8 + blockIdx.x;
    int bh = blockIdx.y;
    int nch = by / 8 + 1;
    int tid = threadIdx.x;
    int row = tid >> 1, half = tid & 1;
    size_t p0 = ((size_t)(bh * 32 + by)) * 4;

    float mf = -1e30f;
    #pragma unroll 4
    for (int chv = 0; chv < 4; chv++)
        if (chv < nch) mf = fmaxf(mf, mpart[(p0 + chv) * 128 + row]);
    float L = 0.f;
    float wch[4];
    #pragma unroll 4
    for (int chv = 0; chv < 4; chv++) {
        if (chv < nch) {
            float w = ex2(mpart[(p0 + chv) * 128 + row] - mf);
            wch[chv] = w;
            L += lpart[(p0 + chv) * 128 + row] * w;
        } else wch[chv] = 0.f;
    }
    float invL = 1.0f / L;

    float acc[32];
    #pragma unroll
    for (int j = 0; j < 32; j++) acc[j] = 0.f;
    #pragma unroll 4
    for (int chv = 0; chv < 4; chv++) {
        if (chv >= nch) break;
        const float* ob = opart + ((p0 + chv) * 128 + row) * DK + half * 32;
        float w = wch[chv];
        #pragma unroll
        for (int j4 = 0; j4 < 8; j4++) {
            float4 vv = *reinterpret_cast<const float4*>(&ob[j4 * 4]);
            acc[j4*4+0] += vv.x * w; acc[j4*4+1] += vv.y * w;
            acc[j4*4+2] += vv.z * w; acc[j4*4+3] += vv.w * w;
        }
    }

    int i = by * 128 + row;
    int bb = bh >> 3, h = bh & 7;
    float* cp = ctx + ((size_t)(bb * SS + i)) * DD + h * 64 + half * 32;
    #pragma unroll
    for (int j4 = 0; j4 < 8; j4++) {
        float4 vv = { tfr(acc[j4*4+0] * invL), tfr(acc[j4*4+1] * invL),
                      tfr(acc[j4*4+2] * invL), tfr(acc[j4*4+3] * invL) };
        *reinterpret_cast<float4*>(&cp[j4 * 4]) = vv;
    }
    if (half == 0) {
        gm[(size_t)bh * SS + i] = mf;
        glinv[(size_t)bh * SS + i] = invL;
    }
}

// ---------------------------------------------------------------------------
// attn writer: lower-triangle compute tiles; each strictly-lower tile ALSO
// zero-fills its mirror upper tile, with the stores issued before the mma so
// they drain while the tensor pipe works. Upper-tile blocks early-exit.
// ---------------------------------------------------------------------------
#define AW_SMEM_WORDS (8704 * 2)
#define AW_SMEM_BYTES (AW_SMEM_WORDS * 4)

__global__ __launch_bounds__(256, 2) void attn_write(
    const float* __restrict__ q, const float* __restrict__ k,
    const float* __restrict__ gm, const float* __restrict__ glinv,
    float* __restrict__ attn)
{
    int bx = blockIdx.x, by = blockIdx.y, bh = blockIdx.z;
    if (bx > by) return;   // upper tiles zeroed by their mirror lower block
    float* ab = attn + (size_t)bh * SS * SS;
    int tid = threadIdx.x;

    extern __shared__ uint32_t sm2[];
    uint32_t* Qs = sm2;
    uint32_t* Ks = sm2 + 8704;
    const float* qb = q + (size_t)bh * SS * DK;
    const float* kb = k + (size_t)bh * SS * DK;

    int lane = tid & 31, warp = tid >> 5;
    int wm = (warp >> 2) * 64, wn = (warp & 3) * 32;
    int r = lane >> 2, c = lane & 3;

    // hoist per-row softmax stats out of the epilogue dependency chain
    float mh[4][2], lh[4][2];
    #pragma unroll
    for (int im = 0; im < 4; im++) {
        int i0 = by * 128 + wm + im * 16 + r;
        mh[im][0] = __ldg(&gm[(size_t)bh * SS + i0]);
        mh[im][1] = __ldg(&gm[(size_t)bh * SS + i0 + 8]);
        lh[im][0] = __ldg(&glinv[(size_t)bh * SS + i0]);
        lh[im][1] = __ldg(&glinv[(size_t)bh * SS + i0 + 8]);
    }

    #pragma unroll 4
    for (int l = tid; l < 2048; l += 256) {
        int rr = l >> 4, c4 = (l & 15) * 4;
        *reinterpret_cast<uint4*>(&Qs[rr * 68 + c4]) =
            *reinterpret_cast<const uint4*>(&qb[(size_t)(by * 128 + rr) * DK + c4]);
        *reinterpret_cast<uint4*>(&Ks[rr * 68 + c4]) =
            *reinterpret_cast<const uint4*>(&kb[(size_t)(bx * 128 + rr) * DK + c4]);
    }

    // zero-fill the mirror upper tile (bx,by): independent stores that drain
    // through the LSU while the mma loop below occupies the tensor pipe.
    if (bx < by) {
        float4 z = { 0.f, 0.f, 0.f, 0.f };
        #pragma unroll 4
        for (int l = tid; l < 4096; l += 256) {
            int rr = l >> 5, c4 = (l & 31) * 4;
            __stcs(reinterpret_cast<float4*>(
                &ab[(size_t)(bx * 128 + rr) * SS + by * 128 + c4]), z);
        }
    }
    __syncthreads();

    float acc[4][4][4];
    #pragma unroll
    for (int im = 0; im < 4; im++)
        #pragma unroll
        for (int in = 0; in < 4; in++)
            #pragma unroll
            for (int qq = 0; qq < 4; qq++) acc[im][in][qq] = 0.f;

    #pragma unroll
    for (int kk = 0; kk < 64; kk += 8) {
        uint32_t a[4][4], b[4][2];
        #pragma unroll
        for (int im = 0; im < 4; im++) {
            int mb = wm + im * 16;
            a[im][0] = Qs[(mb + r) * 68 + kk + c];
            a[im][1] = Qs[(mb + r + 8) * 68 + kk + c];
            a[im][2] = Qs[(mb + r) * 68 + kk + c + 4];
            a[im][3] = Qs[(mb + r + 8) * 68 + kk + c + 4];
        }
        #pragma unroll
        for (int in = 0; in < 4; in++) {
            int nb = wn + in * 8;
            b[in][0] = Ks[(nb + r) * 68 + kk + c];
            b[in][1] = Ks[(nb + r) * 68 + kk + c + 4];
        }
        #pragma unroll
        for (int im = 0; im < 4; im++)
            #pragma unroll
            for (int in = 0; in < 4; in++)
                mma8(acc[im][in], a[im][0], a[im][1], a[im][2], a[im][3],
                     b[in][0], b[in][1]);
    }

    __syncthreads();  // everyone done reading Qs/Ks
    float* Ps = reinterpret_cast<float*>(sm2);
    bool dg = (bx == by);
    #pragma unroll
    for (int im = 0; im < 4; im++) {
        int i0 = by * 128 + wm + im * 16 + r;
        int i1 = i0 + 8;
        int lr0 = wm + im * 16 + r, lr1 = lr0 + 8;
        float m_0 = mh[im][0], li0 = lh[im][0];
        float m_1 = mh[im][1], li1 = lh[im][1];
        #pragma unroll
        for (int in = 0; in < 4; in++) {
            int j = wn + in * 8 + 2 * c;
            int j0 = bx * 128 + j;
            float p0 = ex2(acc[im][in][0] * SCL - m_0) * li0;
            float p1 = ex2(acc[im][in][1] * SCL - m_0) * li0;
            float p2 = ex2(acc[im][in][2] * SCL - m_1) * li1;
            float p3 = ex2(acc[im][in][3] * SCL - m_1) * li1;
            if (dg) {
                if (j0     > i0) p0 = 0.f;
                if (j0 + 1 > i0) p1 = 0.f;
                if (j0     > i1) p2 = 0.f;
                if (j0 + 1 > i1) p3 = 0.f;
            }
            float2 w01 = { p0, p1 };
            float2 w23 = { p2, p3 };
            *reinterpret_cast<float2*>(&Ps[lr0 * 136 + j]) = w01;
            *reinterpret_cast<float2*>(&Ps[lr1 * 136 + j]) = w23;
        }
    }
    __syncthreads();

    #pragma unroll 4
    for (int l = tid; l < 4096; l += 256) {
        int rr = l >> 5, c4 = (l & 31) * 4;
        float4 vv = *reinterpret_cast<const float4*>(&Ps[rr * 136 + c4]);
        __stcs(reinterpret_cast<float4*>(
            &ab[(size_t)(by * 128 + rr) * SS + bx * 128 + c4]), vv);
    }
}

// ---------------------------------------------------------------------------
extern "C" void kernel_launch(void* const* d_in, const int* in_sizes, int n_in,
                              void* d_out, int out_size)
{
    (void)in_sizes; (void)n_in;
    const float* Q  = (const float*)d_in[0];
    const float* K  = (const float*)d_in[1];
    const float* V  = (const float*)d_in[2];
    const float* wq = (const float*)d_in[3];
    const float* bq = (const float*)d_in[4];
    const float* wk = (const float*)d_in[5];
    const float* bk = (const float*)d_in[6];
    const float* wv = (const float*)d_in[7];
    const float* bv = (const float*)d_in[8];
    const float* wo = (const float*)d_in[9];
    const float* bo = (const float*)d_in[10];
    float* out = (float*)d_out;

    const size_t outN  = (size_t)MROWS * DD;
    const size_t attnN = (size_t)BH * SS * SS;

    int write_attn;
    float* attn;
    if ((size_t)out_size >= outN + attnN) {
        attn = out + outN;
        write_attn = 1;
    } else {
        void* p = nullptr;
        cudaGetSymbolAddress(&p, g_attn);
        attn = (float*)p;
        write_attn = 0;
    }

    float *qp, *kp, *vp, *ctxp, *mp, *lp, *op, *mpp, *lpp, *rin, *rw;
    { void* p; cudaGetSymbolAddress(&p, g_q);     qp   = (float*)p; }
    { void* p; cudaGetSymbolAddress(&p, g_k);     kp   = (float*)p; }
    { void* p; cudaGetSymbolAddress(&p, g_v);     vp   = (float*)p; }
    { void* p; cudaGetSymbolAddress(&p, g_ctx);   ctxp = (float*)p; }
    { void* p; cudaGetSymbolAddress(&p, g_m);     mp   = (float*)p; }
    { void* p; cudaGetSymbolAddress(&p, g_linv);  lp   = (float*)p; }
    { void* p; cudaGetSymbolAddress(&p, g_opart); op   = (float*)p; }
    { void* p; cudaGetSymbolAddress(&p, g_mpart); mpp  = (float*)p; }
    { void* p; cudaGetSymbolAddress(&p, g_lpart); lpp  = (float*)p; }
    { void* p; cudaGetSymbolAddress(&p, g_rin);   rin  = (float*)p; }
    { void* p; cudaGetSymbolAddress(&p, g_rw);    rw   = (float*)p; }

    cudaFuncSetAttribute(flash_attn, cudaFuncAttributeMaxDynamicSharedMemorySize,
                         FL_SMEM_BYTES);
    cudaFuncSetAttribute(attn_write, cudaFuncAttributeMaxDynamicSharedMemorySize,
                         AW_SMEM_BYTES);
    cudaFuncSetAttribute(gemm_qkv, cudaFuncAttributeMaxDynamicSharedMemorySize,
                         GEMM_SMEM_BYTES);
    cudaFuncSetAttribute(gemm_out, cudaFuncAttributeMaxDynamicSharedMemorySize,
                         GEMM_SMEM_BYTES);

    dim3 blk(256);
    size_t totalRound = (NINW + NWW) / 4;
    dim3 gQKV(DD / 128, MROWS / 128, 3);
    dim3 gFA(80, BH);
    dim3 gCB(24, BH);
    dim3 gOut(DD / 128, MROWS / 128);

    // Sequential main chain (known-good ordering)
    round_pre<<<(unsigned)(totalRound / 256), blk>>>(Q, K, V, wq, wk, wv, wo, rin, rw);
    gemm_qkv<<<gQKV, blk, GEMM_SMEM_BYTES>>>(rin, rw, bq, bk, bv, qp, kp, vp);
    flash_attn<<<gFA, blk, FL_SMEM_BYTES>>>(qp, kp, vp, ctxp, mp, lp, op, mpp, lpp);
    flash_combine<<<gCB, blk>>>(op, mpp, lpp, ctxp, mp, lp);

    if (write_attn) {
        // Fork ONLY the small tensor-bound gemm_out beside the DRAM-bound attn_write.
        cudaStream_t s2;
        cudaStreamCreate(&s2);
        cudaEvent_t eB, eC;
        cudaEventCreateWithFlags(&eB, cudaEventDisableTiming);
        cudaEventCreateWithFlags(&eC, cudaEventDisableTiming);

        cudaEventRecord(eB, 0);
        cudaStreamWaitEvent(s2, eB, 0);
        gemm_out<<<gOut, blk, GEMM_SMEM_BYTES, s2>>>(ctxp, rw, bo, out);
        cudaEventRecord(eC, s2);

        dim3 gAW(SS / 128, SS / 128, BH);
        attn_write<<<gAW, blk, AW_SMEM_BYTES>>>(qp, kp, mp, lp, attn);

        cudaStreamWaitEvent(0, eC, 0);
    } else {
        gemm_out<<<gOut, blk, GEMM_SMEM_BYTES>>>(ctxp, rw, bo, out);
    }
}